// round 15
// baseline (speedup 1.0000x reference)
#include <cuda_runtime.h>
#include <cuda_fp16.h>
#include <math.h>
#include <stdint.h>

#define NN   16384
#define NE   262144
#define NG   64
#define LMAXC 320
#define EMBD 256
#define FFND 1024
#define NHD  8
#define DHD  32
#define NTOK (LMAXC*NG)
#define MTOT 16512            // 16384 nodes + 64 pad reps + 64 zero rows (129*128)

// ---------------- scratch (device globals; no allocation allowed) ----------
__device__ int   g_rowptr[NN + 1];
__device__ int   g_cnt[NN];
__device__ int   g_csrc[NE];
__device__ int   g_bsum[64];
__device__ float g_comb0[NN*32];
__device__ float g_wsg0[32*256];
__device__ __align__(256) __half g_comb1h[NN*512];
__device__ __align__(256) __half g_comb2h[NN*512];
__device__ float g_hp [MTOT*EMBD];
__device__ __align__(256) __half g_hph[MTOT*EMBD];
__device__ __align__(256) __half g_qkvh[MTOT*768];
__device__ __align__(256) __half g_oh[MTOT*EMBD];
__device__ __align__(256) __half g_midh[MTOT*FFND];
__device__ __align__(256) __half g_wsg1t[256*512];
__device__ __align__(256) __half g_wsg2t[256*512];
__device__ __align__(256) __half g_wqkvt[4*768*256];
__device__ __align__(256) __half g_wot[4*256*256];
__device__ __align__(256) __half g_w1t[4*1024*256];
__device__ __align__(256) __half g_w2t[4*256*1024];
__device__ float g_bqkv[4*768];

// =================== CSR build =============================================
__global__ void degi_kernel(const int* __restrict__ ei, int* __restrict__ cnt) {
    int e = blockIdx.x * blockDim.x + threadIdx.x;
    if (e < NE) atomicAdd(&cnt[ei[NE + e]], 1);
}

__global__ void scan_local(int* __restrict__ cnt, int* __restrict__ rowptr,
                           int* __restrict__ bsum) {
    __shared__ int wsum[8];
    int n = blockIdx.x * 256 + threadIdx.x;
    int lane = threadIdx.x & 31, w = threadIdx.x >> 5;
    int c = cnt[n];
    int inc = c;
#pragma unroll
    for (int off = 1; off < 32; off <<= 1) {
        int v = __shfl_up_sync(0xffffffffu, inc, off);
        if (lane >= off) inc += v;
    }
    if (lane == 31) wsum[w] = inc;
    __syncthreads();
    if (threadIdx.x == 0) {
        int acc = 0;
#pragma unroll
        for (int i = 0; i < 8; i++) { int t = wsum[i]; wsum[i] = acc; acc += t; }
        bsum[blockIdx.x] = acc;
    }
    __syncthreads();
    rowptr[n] = inc - c + wsum[w];
    cnt[n] = 0;
}

__global__ void scan_bsum(int* __restrict__ bsum) {
    int lane = threadIdx.x;
    int a = bsum[lane], b = bsum[lane + 32];
    int inc = a;
#pragma unroll
    for (int off = 1; off < 32; off <<= 1) {
        int v = __shfl_up_sync(0xffffffffu, inc, off);
        if (lane >= off) inc += v;
    }
    int tot0 = __shfl_sync(0xffffffffu, inc, 31);
    int inc2 = b;
#pragma unroll
    for (int off = 1; off < 32; off <<= 1) {
        int v = __shfl_up_sync(0xffffffffu, inc2, off);
        if (lane >= off) inc2 += v;
    }
    bsum[lane] = inc - a;
    bsum[lane + 32] = tot0 + inc2 - b;
}

__global__ void scan_add(int* __restrict__ rowptr, const int* __restrict__ bsum) {
    int n = blockIdx.x * 256 + threadIdx.x;
    rowptr[n] += bsum[blockIdx.x];
    if (n == 0) rowptr[NN] = NE;
}

__global__ void fill_kernel(const int* __restrict__ ei, int* __restrict__ cnt,
                            int* __restrict__ csrc) {
    int e = blockIdx.x * blockDim.x + threadIdx.x;
    if (e >= NE) return;
    int d = ei[NE + e];
    int pos = atomicAdd(&cnt[d], 1);
    csrc[g_rowptr[d] + pos] = ei[e];
}

__global__ void misc_pack(float* __restrict__ hp, __half* __restrict__ hph,
                          __half* __restrict__ oh,
                          const float* __restrict__ Ws, const float* __restrict__ Wn,
                          float* __restrict__ w0out,
                          const float* __restrict__ bq, const float* __restrict__ bk,
                          const float* __restrict__ bv, float* __restrict__ bout) {
    int b = blockIdx.x;
    int tid = threadIdx.x;
    if (b < 128) {
        long o = (long)(NN + b) * EMBD + tid;
        hp[o] = 0.0f;
        hph[o] = __float2half(0.0f);
        oh[o] = __float2half(0.0f);
    } else if (b < 160) {
        int k = b - 128;
        w0out[k * 256 + tid] = (k < 16) ? Ws[k * 256 + tid] : Wn[(k - 16) * 256 + tid];
    } else {
        int idx = b - 160;
        int s = idx % 3, l = idx / 3;
        const float* src = (s == 0) ? bq : ((s == 1) ? bk : bv);
        bout[l * 768 + s * 256 + tid] = src[l * 256 + tid];
    }
}

__global__ void scatter_out(const float* __restrict__ hp, const int* __restrict__ batches,
                            float* __restrict__ out) {
    int l = blockIdx.x, g = blockIdx.y;
    int st = batches[g];
    int len = batches[g + 1] - st;
    long src = (l < len) ? (long)(st + l) : (long)(NN + g);
    out[((long)l * NG + g) * EMBD + threadIdx.x] = hp[src * EMBD + threadIdx.x];
}

// =================== SAGE layer-0 input assembly ===========================
__global__ void agg0_kernel(const float* __restrict__ x, float* __restrict__ comb0) {
    int w = threadIdx.x >> 5;
    int lane = threadIdx.x & 31;
    int node = blockIdx.x * 8 + w;
    if (lane >= 16) return;
    int s0 = g_rowptr[node], s1 = g_rowptr[node + 1];
    float sum = 0.f;
    for (int j = s0; j < s1; j++) sum += x[g_csrc[j] * 16 + lane];
    comb0[node * 32 + lane] = x[node * 16 + lane];
    comb0[node * 32 + 16 + lane] = sum / fmaxf((float)(s1 - s0), 1.f);
}

__global__ void agg_csr_h(__half* __restrict__ feat) {
    int node = blockIdx.x;
    int c = threadIdx.x;
    const __half2* f2 = (const __half2*)feat;
    int s0 = g_rowptr[node], s1 = g_rowptr[node + 1];
    float sx = 0.f, sy = 0.f;
    int j = s0;
    for (; j + 4 <= s1; j += 4) {
        float2 v0 = __half22float2(f2[(long)g_csrc[j]     * 256 + c]);
        float2 v1 = __half22float2(f2[(long)g_csrc[j + 1] * 256 + c]);
        float2 v2 = __half22float2(f2[(long)g_csrc[j + 2] * 256 + c]);
        float2 v3 = __half22float2(f2[(long)g_csrc[j + 3] * 256 + c]);
        sx += (v0.x + v1.x) + (v2.x + v3.x);
        sy += (v0.y + v1.y) + (v2.y + v3.y);
    }
    for (; j < s1; j++) {
        float2 a = __half22float2(f2[(long)g_csrc[j] * 256 + c]);
        sx += a.x; sy += a.y;
    }
    float inv = 1.f / fmaxf((float)(s1 - s0), 1.f);
    ((__half2*)feat)[(long)node * 256 + 128 + c] = __floats2half2_rn(sx * inv, sy * inv);
}

// ---- all 10 weight transposes (fp32 [K,N] -> half [N,K]) in ONE launch ----
struct TJobs {
    const float* src[10];
    __half*      dst[10];
    int gx[10], gy[10], N[10], ldd[10];
    long sls[10], dls[10];
    int base[11];
};

__global__ void transpose_all(TJobs J) {
    __shared__ float t[32][33];
    int b = blockIdx.x;
    int j = 0;
#pragma unroll
    for (int i = 0; i < 10; i++) if (b >= J.base[i + 1]) j = i + 1;
    int local = b - J.base[j];
    int tpz = J.gx[j] * J.gy[j];
    int z = local / tpz, rem = local - z * tpz;
    int ky = rem / J.gx[j], nx = rem - ky * J.gx[j];
    const float* s = J.src[j] + (long)z * J.sls[j];
    __half* d = J.dst[j] + (long)z * J.dls[j];
    int N = J.N[j], ldd = J.ldd[j];
    int k0 = ky * 32, n0 = nx * 32;
    int tx = threadIdx.x, ty = threadIdx.y;
#pragma unroll
    for (int i = 0; i < 32; i += 8)
        t[ty + i][tx] = s[(long)(k0 + ty + i) * N + n0 + tx];
    __syncthreads();
#pragma unroll
    for (int i = 0; i < 32; i += 8)
        d[(long)(n0 + ty + i) * ldd + k0 + tx] = __float2half(t[tx][ty + i]);
}

// ================= fp32 GEMM K=32 for SAGE layer 0, half output =============
#define BM 64
#define BN 64
__global__ void gemm32h_kernel(const float* __restrict__ A, const float* __restrict__ B,
                               const float* __restrict__ bias, __half* __restrict__ C,
                               int ldc) {
    __shared__ float As[16][BM + 1];
    __shared__ float Bs[16][BN];
    int bm = blockIdx.y * BM;
    int bn = blockIdx.x * BN;
    int tid = threadIdx.x;
    int tx = tid & 15;
    int ty = tid >> 4;
    float r[4][4];
#pragma unroll
    for (int i = 0; i < 4; i++)
#pragma unroll
        for (int j = 0; j < 4; j++) r[i][j] = 0.0f;

    for (int k0 = 0; k0 < 32; k0 += 16) {
#pragma unroll
        for (int i = 0; i < 4; i++) {
            int idx = tid + i * 256;
            int rr = idx >> 4, cc = idx & 15;
            As[cc][rr] = A[(long)(bm + rr) * 32 + k0 + cc];
        }
#pragma unroll
        for (int i = 0; i < 4; i++) {
            int idx = tid + i * 256;
            int rr = idx >> 6, cc = idx & 63;
            Bs[rr][cc] = B[(long)(k0 + rr) * 256 + bn + cc];
        }
        __syncthreads();
#pragma unroll
        for (int kk = 0; kk < 16; kk++) {
            float a[4], b[4];
#pragma unroll
            for (int i = 0; i < 4; i++) a[i] = As[kk][ty * 4 + i];
#pragma unroll
            for (int j = 0; j < 4; j++) b[j] = Bs[kk][tx * 4 + j];
#pragma unroll
            for (int i = 0; i < 4; i++)
#pragma unroll
                for (int j = 0; j < 4; j++) r[i][j] = fmaf(a[i], b[j], r[i][j]);
        }
        __syncthreads();
    }
#pragma unroll
    for (int i = 0; i < 4; i++) {
        long row = bm + ty * 4 + i;
        __half2* C2 = (__half2*)(C + row * ldc + bn + tx * 4);
#pragma unroll
        for (int j = 0; j < 4; j += 2) {
            int col = bn + tx * 4 + j;
            float v0 = fmaxf(r[i][j] + bias[col], 0.f);
            float v1 = fmaxf(r[i][j + 1] + bias[col + 1], 0.f);
            C2[j >> 1] = __floats2half2_rn(v0, v1);
        }
    }
}

// ================= FP16 tensor-core GEMM common helpers ======================
#define HSTR 72
#define HBUF (128*HSTR)
#define HSMEM (4*HBUF*2)

#define CPA16(dst, src) asm volatile("cp.async.cg.shared.global [%0], [%1], 16;" :: "r"(dst), "l"(src))

__device__ __forceinline__ void ldsm4(uint32_t (&r)[4], uint32_t addr) {
    asm volatile("ldmatrix.sync.aligned.m8n8.x4.shared.b16 {%0,%1,%2,%3}, [%4];"
                 : "=r"(r[0]), "=r"(r[1]), "=r"(r[2]), "=r"(r[3]) : "r"(addr));
}
__device__ __forceinline__ void ldsm4t(uint32_t (&r)[4], uint32_t addr) {
    asm volatile("ldmatrix.sync.aligned.m8n8.x4.trans.shared.b16 {%0,%1,%2,%3}, [%4];"
                 : "=r"(r[0]), "=r"(r[1]), "=r"(r[2]), "=r"(r[3]) : "r"(addr));
}

#define HMMA(d, a, b0, b1) asm volatile( \
    "mma.sync.aligned.m16n8k16.row.col.f32.f16.f16.f32 " \
    "{%0,%1,%2,%3}, {%4,%5,%6,%7}, {%8,%9}, {%0,%1,%2,%3};" \
    : "+f"(d[0]), "+f"(d[1]), "+f"(d[2]), "+f"(d[3]) \
    : "r"(a[0]), "r"(a[1]), "r"(a[2]), "r"(a[3]), "r"(b0), "r"(b1))

__device__ __forceinline__ uint32_t packh2(float a, float b) {
    __half2 h = __floats2half2_rn(a, b);
    return *(uint32_t*)&h;
}

// ========== hgemm64: 128x64 tile (SAGE layers, N=256) ========================
#define A64BUF (128*HSTR)
#define B64BUF (64*HSTR)
#define HSMEM64 ((2*A64BUF + 2*B64BUF)*2)

__global__ void __launch_bounds__(256, 2)
hgemm64(const __half* __restrict__ A, const __half* __restrict__ Bt,
        const float* __restrict__ bias, void* __restrict__ Cv,
        int M, int N, int K, int lda, int ldc, int relu, int outh,
        float* __restrict__ outf) {
    extern __shared__ __half shh[];
    const int tid  = threadIdx.x;
    const int lane = tid & 31;
    const int wid  = tid >> 5;
    const int wr   = wid >> 1;
    const int wc   = wid & 1;
    const int bm   = blockIdx.y * 128;
    const int bn   = blockIdx.x * 64;

    uint32_t sbase = (uint32_t)__cvta_generic_to_shared(shh);

    float acc[2][4][4];
#pragma unroll
    for (int mt = 0; mt < 2; mt++)
#pragma unroll
        for (int nt = 0; nt < 4; nt++)
#pragma unroll
            for (int r = 0; r < 4; r++) acc[mt][nt][r] = 0.0f;

#define HLOAD64(buf, k0)                                                        \
    do {                                                                        \
        _Pragma("unroll")                                                       \
        for (int i = 0; i < 4; i++) {                                           \
            int idx = tid + i * 256;                                            \
            int r = idx >> 3, c = (idx & 7) << 3;                               \
            CPA16(sbase + (uint32_t)((buf) * A64BUF + r * HSTR + c) * 2u,       \
                  A + (long)(bm + r) * lda + (k0) + c);                         \
        }                                                                       \
        _Pragma("unroll")                                                       \
        for (int i = 0; i < 2; i++) {                                           \
            int idx = tid + i * 256;                                            \
            int r = idx >> 3, c = (idx & 7) << 3;                               \
            CPA16(sbase + (uint32_t)(2 * A64BUF + (buf) * B64BUF + r * HSTR + c) * 2u, \
                  Bt + (long)(bn + r) * K + (k0) + c);                          \
        }                                                                       \
        asm volatile("cp.async.commit_group;");                                 \
    } while (0)

    const int nk = K >> 6;
    HLOAD64(0, 0);

    const int arow = wr * 32 + (lane & 15);
    const int ach  = (lane >> 4) << 3;
    const int brow16 = wc * 32 + (lane & 15);
    const int bch16  = (lane >> 4) << 3;

    for (int it = 0; it < nk; it++) {
        int cur = it & 1;
        if (it + 1 < nk) {
            HLOAD64(cur ^ 1, (it + 1) << 6);
            asm volatile("cp.async.wait_group 1;");
        } else {
            asm volatile("cp.async.wait_group 0;");
        }
        __syncthreads();

        uint32_t aB = sbase + (uint32_t)(cur * A64BUF) * 2u;
        uint32_t bB = sbase + (uint32_t)(2 * A64BUF + cur * B64BUF) * 2u;

#pragma unroll
        for (int ks = 0; ks < 4; ks++) {
            uint32_t af[2][4], bf[4][2];
#pragma unroll
            for (int mt = 0; mt < 2; mt++)
                ldsm4(af[mt], aB + (uint32_t)((arow + mt * 16) * HSTR + ks * 16 + ach) * 2u);
#pragma unroll
            for (int np = 0; np < 2; np++) {
                uint32_t br[4];
                ldsm4(br, bB + (uint32_t)((brow16 + np * 16) * HSTR + ks * 16 + bch16) * 2u);
                bf[2 * np][0] = br[0];     bf[2 * np][1] = br[2];
                bf[2 * np + 1][0] = br[1]; bf[2 * np + 1][1] = br[3];
            }
#pragma unroll
            for (int mt = 0; mt < 2; mt++)
#pragma unroll
                for (int nt = 0; nt < 4; nt++)
                    HMMA(acc[mt][nt], af[mt], bf[nt][0], bf[nt][1]);
        }
        __syncthreads();
    }

#pragma unroll
    for (int mt = 0; mt < 2; mt++) {
        long row = bm + wr * 32 + mt * 16 + (lane >> 2);
#pragma unroll
        for (int nt = 0; nt < 4; nt++) {
            int col = bn + wc * 32 + nt * 8 + ((lane & 3) << 1);
            float b0 = bias[col], b1 = bias[col + 1];
            float v0 = acc[mt][nt][0] + b0, v1 = acc[mt][nt][1] + b1;
            float v2 = acc[mt][nt][2] + b0, v3 = acc[mt][nt][3] + b1;
            if (relu) { v0 = fmaxf(v0, 0.f); v1 = fmaxf(v1, 0.f);
                        v2 = fmaxf(v2, 0.f); v3 = fmaxf(v3, 0.f); }
            if (outf) {
                *(float2*)(outf + row * ldc + col) = make_float2(v0, v1);
                *(float2*)(outf + (row + 8) * ldc + col) = make_float2(v2, v3);
            }
            if (outh) {
                __half2* C2 = (__half2*)Cv;
                C2[(row * ldc + col) >> 1]       = __floats2half2_rn(v0, v1);
                C2[((row + 8) * ldc + col) >> 1] = __floats2half2_rn(v2, v3);
            }
        }
    }
#undef HLOAD64
}

// ======= hgemm256: 128x256 tile, bias(+relu) -> half (QKV / FFN1) ===========
#define A256 (128*HSTR)
#define B256 (256*HSTR)
#define HSMEM256 ((2*A256 + 2*B256)*2)

__global__ void __launch_bounds__(256, 1)
hgemm256(const __half* __restrict__ A, const __half* __restrict__ Bt,
         const float* __restrict__ bias, __half* __restrict__ C,
         int K, int lda, int ldc, int relu) {
    extern __shared__ __half shh[];
    const int tid  = threadIdx.x;
    const int lane = tid & 31;
    const int wid  = tid >> 5;
    const int wr   = wid >> 2;   // 0..1 (64 rows each)
    const int wc   = wid & 3;    // 0..3 (64 cols each)
    const long bm  = (long)blockIdx.y * 128;
    const int  bn  = blockIdx.x * 256;

    uint32_t sbase = (uint32_t)__cvta_generic_to_shared(shh);

    float acc[4][8][4];
#pragma unroll
    for (int mt = 0; mt < 4; mt++)
#pragma unroll
        for (int nt = 0; nt < 8; nt++)
#pragma unroll
            for (int r = 0; r < 4; r++) acc[mt][nt][r] = 0.0f;

#define LOAD256(buf, k0)                                                        \
    do {                                                                        \
        _Pragma("unroll")                                                       \
        for (int i = 0; i < 4; i++) {                                           \
            int idx = tid + i * 256;                                            \
            int r = idx >> 3, c = (idx & 7) << 3;                               \
            CPA16(sbase + (uint32_t)((buf) * A256 + r * HSTR + c) * 2u,         \
                  A + (bm + r) * lda + (k0) + c);                               \
        }                                                                       \
        _Pragma("unroll")                                                       \
        for (int i = 0; i < 8; i++) {                                           \
            int idx = tid + i * 256;                                            \
            int r = idx >> 3, c = (idx & 7) << 3;                               \
            CPA16(sbase + (uint32_t)(2 * A256 + (buf) * B256 + r * HSTR + c) * 2u,\
                  Bt + (long)(bn + r) * K + (k0) + c);                          \
        }                                                                       \
        asm volatile("cp.async.commit_group;");                                 \
    } while (0)

    const int nk = K >> 6;
    LOAD256(0, 0);

    const int arowb = wr * 64 + (lane & 15);
    const int ach   = (lane >> 4) << 3;
    const int browb = wc * 64 + (lane & 7) + ((lane >> 4) << 3);
    const int bch   = lane & 8;

    for (int it = 0; it < nk; it++) {
        int cur = it & 1;
        if (it + 1 < nk) {
            LOAD256(cur ^ 1, (it + 1) << 6);
            asm volatile("cp.async.wait_group 1;");
        } else {
            asm volatile("cp.async.wait_group 0;");
        }
        __syncthreads();

        uint32_t aB = sbase + (uint32_t)(cur * A256) * 2u;
        uint32_t bB = sbase + (uint32_t)(2 * A256 + cur * B256) * 2u;

#pragma unroll
        for (int ks = 0; ks < 4; ks++) {
            uint32_t af[4][4];
#pragma unroll
            for (int mt = 0; mt < 4; mt++)
                ldsm4(af[mt], aB + (uint32_t)((arowb + mt * 16) * HSTR + ks * 16 + ach) * 2u);
#pragma unroll
            for (int np = 0; np < 4; np++) {
                uint32_t kf[4];
                ldsm4(kf, bB + (uint32_t)((browb + np * 16) * HSTR + ks * 16 + bch) * 2u);
#pragma unroll
                for (int mt = 0; mt < 4; mt++) {
                    HMMA(acc[mt][2 * np],     af[mt], kf[0], kf[1]);
                    HMMA(acc[mt][2 * np + 1], af[mt], kf[2], kf[3]);
                }
            }
        }
        __syncthreads();
    }

    const int q = lane >> 2, t2 = (lane & 3) << 1;
#pragma unroll
    for (int mt = 0; mt < 4; mt++) {
        long r0 = bm + wr * 64 + mt * 16 + q;
        long r1 = r0 + 8;
#pragma unroll
        for (int nt = 0; nt < 8; nt++) {
            int col = bn + wc * 64 + nt * 8 + t2;
            float b0 = bias[col], b1 = bias[col + 1];
            float v0 = acc[mt][nt][0] + b0, v1 = acc[mt][nt][1] + b1;
            float v2 = acc[mt][nt][2] + b0, v3 = acc[mt][nt][3] + b1;
            if (relu) { v0 = fmaxf(v0, 0.f); v1 = fmaxf(v1, 0.f);
                        v2 = fmaxf(v2, 0.f); v3 = fmaxf(v3, 0.f); }
            *(__half2*)(C + r0 * ldc + col) = __floats2half2_rn(v0, v1);
            *(__half2*)(C + r1 * ldc + col) = __floats2half2_rn(v2, v3);
        }
    }
#undef LOAD256
}

// ===== hgemm_ln: 64x256 tile GEMM + bias + residual + LayerNorm epilogue ====
#define LNA (64*HSTR)
#define LNB (256*HSTR)
#define HSMEM_LN ((2*LNA + 2*LNB)*2)

__global__ void __launch_bounds__(256, 2)
hgemm_ln(const __half* __restrict__ A, const __half* __restrict__ Bt,
         const float* __restrict__ bias, const float* __restrict__ resid,
         const float* __restrict__ gamma, const float* __restrict__ beta,
         float* __restrict__ outf, __half* __restrict__ outh, int K) {
    extern __shared__ __half shh[];
    __shared__ float red[64][4];
    const int tid  = threadIdx.x;
    const int lane = tid & 31;
    const int wid  = tid >> 5;
    const int wr   = wid >> 2;
    const int wc   = wid & 3;
    const long bm  = (long)blockIdx.x * 64;

    uint32_t sbase = (uint32_t)__cvta_generic_to_shared(shh);

    float acc[2][8][4];
#pragma unroll
    for (int mt = 0; mt < 2; mt++)
#pragma unroll
        for (int nt = 0; nt < 8; nt++)
#pragma unroll
            for (int r = 0; r < 4; r++) acc[mt][nt][r] = 0.0f;

#define LNLOAD(buf, k0)                                                         \
    do {                                                                        \
        _Pragma("unroll")                                                       \
        for (int i = 0; i < 2; i++) {                                           \
            int idx = tid + i * 256;                                            \
            int r = idx >> 3, c = (idx & 7) << 3;                               \
            CPA16(sbase + (uint32_t)((buf) * LNA + r * HSTR + c) * 2u,          \
                  A + (bm + r) * K + (k0) + c);                                 \
        }                                                                       \
        _Pragma("unroll")                                                       \
        for (int i = 0; i < 8; i++) {                                           \
            int idx = tid + i * 256;                                            \
            int r = idx >> 3, c = (idx & 7) << 3;                               \
            CPA16(sbase + (uint32_t)(2 * LNA + (buf) * LNB + r * HSTR + c) * 2u,\
                  Bt + (long)r * K + (k0) + c);                                 \
        }                                                                       \
        asm volatile("cp.async.commit_group;");                                 \
    } while (0)

    const int nk = K >> 6;
    LNLOAD(0, 0);

    const int arowb = wr * 32 + (lane & 15);
    const int ach   = (lane >> 4) << 3;
    const int browb = wc * 64 + (lane & 7) + ((lane >> 4) << 3);
    const int bch   = lane & 8;

    for (int it = 0; it < nk; it++) {
        int cur = it & 1;
        if (it + 1 < nk) {
            LNLOAD(cur ^ 1, (it + 1) << 6);
            asm volatile("cp.async.wait_group 1;");
        } else {
            asm volatile("cp.async.wait_group 0;");
        }
        __syncthreads();

        uint32_t aB = sbase + (uint32_t)(cur * LNA) * 2u;
        uint32_t bB = sbase + (uint32_t)(2 * LNA + cur * LNB) * 2u;

#pragma unroll
        for (int ks = 0; ks < 4; ks++) {
            uint32_t af[2][4];
#pragma unroll
            for (int mt = 0; mt < 2; mt++)
                ldsm4(af[mt], aB + (uint32_t)((arowb + mt * 16) * HSTR + ks * 16 + ach) * 2u);
#pragma unroll
            for (int np = 0; np < 4; np++) {
                uint32_t kf[4];
                ldsm4(kf, bB + (uint32_t)((browb + np * 16) * HSTR + ks * 16 + bch) * 2u);
#pragma unroll
                for (int mt = 0; mt < 2; mt++) {
                    HMMA(acc[mt][2 * np],     af[mt], kf[0], kf[1]);
                    HMMA(acc[mt][2 * np + 1], af[mt], kf[2], kf[3]);
                }
            }
        }
        __syncthreads();
    }

    const int q = lane >> 2, t2 = (lane & 3) << 1;
#pragma unroll
    for (int mt = 0; mt < 2; mt++) {
        long r0 = bm + wr * 32 + mt * 16 + q;
        long r1 = r0 + 8;
        float s0 = 0.f, s1 = 0.f;
#pragma unroll
        for (int nt = 0; nt < 8; nt++) {
            int col = wc * 64 + nt * 8 + t2;
            float b0 = bias[col], b1 = bias[col + 1];
            float2 q0 = *(const float2*)(resid + r0 * 256 + col);
            float2 q1 = *(const float2*)(resid + r1 * 256 + col);
            acc[mt][nt][0] += b0 + q0.x; acc[mt][nt][1] += b1 + q0.y;
            acc[mt][nt][2] += b0 + q1.x; acc[mt][nt][3] += b1 + q1.y;
            s0 += acc[mt][nt][0] + acc[mt][nt][1];
            s1 += acc[mt][nt][2] + acc[mt][nt][3];
        }
        s0 += __shfl_xor_sync(0xffffffffu, s0, 1);
        s0 += __shfl_xor_sync(0xffffffffu, s0, 2);
        s1 += __shfl_xor_sync(0xffffffffu, s1, 1);
        s1 += __shfl_xor_sync(0xffffffffu, s1, 2);
        int lr = wr * 32 + mt * 16 + q;
        if ((lane & 3) == 0) { red[lr][wc] = s0; red[lr + 8][wc] = s1; }
    }
    __syncthreads();
    float mean[2][2];
#pragma unroll
    for (int mt = 0; mt < 2; mt++) {
        int lr = wr * 32 + mt * 16 + q;
        mean[mt][0] = (red[lr][0] + red[lr][1] + red[lr][2] + red[lr][3]) * (1.0f / EMBD);
        mean[mt][1] = (red[lr + 8][0] + red[lr + 8][1] + red[lr + 8][2] + red[lr + 8][3]) * (1.0f / EMBD);
    }
    __syncthreads();
#pragma unroll
    for (int mt = 0; mt < 2; mt++) {
        float s0 = 0.f, s1 = 0.f;
#pragma unroll
        for (int nt = 0; nt < 8; nt++) {
            float d0 = acc[mt][nt][0] - mean[mt][0];
            float d1 = acc[mt][nt][1] - mean[mt][0];
            float d2 = acc[mt][nt][2] - mean[mt][1];
            float d3 = acc[mt][nt][3] - mean[mt][1];
            s0 += d0 * d0 + d1 * d1;
            s1 += d2 * d2 + d3 * d3;
        }
        s0 += __shfl_xor_sync(0xffffffffu, s0, 1);
        s0 += __shfl_xor_sync(0xffffffffu, s0, 2);
        s1 += __shfl_xor_sync(0xffffffffu, s1, 1);
        s1 += __shfl_xor_sync(0xffffffffu, s1, 2);
        int lr = wr * 32 + mt * 16 + q;
        if ((lane & 3) == 0) { red[lr][wc] = s0; red[lr + 8][wc] = s1; }
    }
    __syncthreads();
#pragma unroll
    for (int mt = 0; mt < 2; mt++) {
        int lr = wr * 32 + mt * 16 + q;
        float rstd0 = rsqrtf((red[lr][0] + red[lr][1] + red[lr][2] + red[lr][3]) * (1.0f / EMBD) + 1e-5f);
        float rstd1 = rsqrtf((red[lr + 8][0] + red[lr + 8][1] + red[lr + 8][2] + red[lr + 8][3]) * (1.0f / EMBD) + 1e-5f);
        long r0 = bm + lr;
        long r1 = r0 + 8;
#pragma unroll
        for (int nt = 0; nt < 8; nt++) {
            int col = wc * 64 + nt * 8 + t2;
            float g0 = gamma[col], g1 = gamma[col + 1];
            float e0 = beta[col],  e1 = beta[col + 1];
            float o0 = (acc[mt][nt][0] - mean[mt][0]) * rstd0 * g0 + e0;
            float o1 = (acc[mt][nt][1] - mean[mt][0]) * rstd0 * g1 + e1;
            float o2 = (acc[mt][nt][2] - mean[mt][1]) * rstd1 * g0 + e0;
            float o3 = (acc[mt][nt][3] - mean[mt][1]) * rstd1 * g1 + e1;
            *(float2*)(outf + r0 * 256 + col) = make_float2(o0, o1);
            *(float2*)(outf + r1 * 256 + col) = make_float2(o2, o3);
            if (outh) {
                *(__half2*)(outh + r0 * 256 + col) = __floats2half2_rn(o0, o1);
                *(__half2*)(outh + r1 * 256 + col) = __floats2half2_rn(o2, o3);
            }
        }
    }
#undef LNLOAD
}

// ============ compact flash attention + fused pad-rep: block per (g, h) =====
#define ATT_SMEM (2*320*40*2 + 320*4)

__global__ void __launch_bounds__(128, 4)
attn_mma(const __half* __restrict__ qkv, const int* __restrict__ batches,
         __half* __restrict__ oh) {
    int g = blockIdx.x, h = blockIdx.y;
    int st = batches[g];
    int len = batches[g + 1] - st;
    extern __shared__ __half smh[];
    uint32_t sb = (uint32_t)__cvta_generic_to_shared(smh);
    const uint32_t voff = 320u * 40u * 2u;
    float* spf = (float*)(smh + 2 * 320 * 40);
    __shared__ float qsh[DHD];
    __shared__ float s_sm;
    __shared__ float av[4][DHD];

    int tid = threadIdx.x;
    for (int idx = tid; idx < len * 4; idx += 128) {
        int l = idx >> 2, c = idx & 3;
        const __half* srcK = qkv + (long)(st + l) * 768 + 256 + h * 32 + c * 8;
        uint32_t d = (uint32_t)(l * 40 + c * 8) * 2u;
        CPA16(sb + d, srcK);
        CPA16(sb + voff + d, srcK + 256);
    }
    asm volatile("cp.async.commit_group;");
    if (tid < DHD)
        qsh[tid] = __half2float(qkv[(long)(NN + g) * 768 + h * 32 + tid]);
    asm volatile("cp.async.wait_group 0;");
    __syncthreads();

    const int w = tid >> 5, lane = tid & 31;
    const int r = lane >> 2, t = lane & 3;
    const int nch = len >> 6;
    const int ntiles = len >> 4;
    const float scale = 0.17677669529663687f;

    for (int mt = w; mt < ntiles; mt += 4) {
        long q0row = (long)(st + mt * 16 + r);
        uint32_t qf[2][4];
        {
            const __half* q0 = qkv + q0row * 768 + h * 32;
            const __half* q1 = q0 + 8L * 768;
#pragma unroll
            for (int ks = 0; ks < 2; ks++) {
                int c0 = ks * 16 + 2 * t;
                qf[ks][0] = *(const uint32_t*)(q0 + c0);
                qf[ks][1] = *(const uint32_t*)(q1 + c0);
                qf[ks][2] = *(const uint32_t*)(q0 + c0 + 8);
                qf[ks][3] = *(const uint32_t*)(q1 + c0 + 8);
            }
        }
        float o_[4][4];
#pragma unroll
        for (int nt = 0; nt < 4; nt++)
#pragma unroll
            for (int j = 0; j < 4; j++) o_[nt][j] = 0.f;
        float mx0 = -3e38f, mx1 = -3e38f, sm0 = 0.f, sm1 = 0.f;

        for (int ch = 0; ch < nch; ch++) {
            int base = ch << 6;
            float s[8][4];
#pragma unroll
            for (int nt = 0; nt < 8; nt++)
#pragma unroll
                for (int j = 0; j < 4; j++) s[nt][j] = 0.f;

#pragma unroll
            for (int ks = 0; ks < 2; ks++) {
#pragma unroll
                for (int np = 0; np < 4; np++) {
                    uint32_t kf[4];
                    int krow = base + np * 16 + (lane & 7) + ((lane >> 4) << 3);
                    int kcol = ks * 16 + (lane & 8);
                    ldsm4(kf, sb + (uint32_t)(krow * 40 + kcol) * 2u);
                    HMMA(s[2 * np],     qf[ks], kf[0], kf[1]);
                    HMMA(s[2 * np + 1], qf[ks], kf[2], kf[3]);
                }
            }

            float cm0 = -3e38f, cm1 = -3e38f;
#pragma unroll
            for (int nt = 0; nt < 8; nt++) {
                cm0 = fmaxf(cm0, fmaxf(s[nt][0], s[nt][1]));
                cm1 = fmaxf(cm1, fmaxf(s[nt][2], s[nt][3]));
            }
            cm0 = fmaxf(cm0, __shfl_xor_sync(0xffffffffu, cm0, 1));
            cm0 = fmaxf(cm0, __shfl_xor_sync(0xffffffffu, cm0, 2));
            cm1 = fmaxf(cm1, __shfl_xor_sync(0xffffffffu, cm1, 1));
            cm1 = fmaxf(cm1, __shfl_xor_sync(0xffffffffu, cm1, 2));
            float nm0 = fmaxf(mx0, cm0), nm1 = fmaxf(mx1, cm1);
            float corr0 = __expf((mx0 - nm0) * scale);
            float corr1 = __expf((mx1 - nm1) * scale);
            mx0 = nm0; mx1 = nm1;

            uint32_t pf[4][4];
            float ps0 = 0.f, ps1 = 0.f;
#pragma unroll
            for (int kf = 0; kf < 4; kf++) {
                float p00 = __expf((s[2 * kf][0] - nm0) * scale);
                float p01 = __expf((s[2 * kf][1] - nm0) * scale);
                float p02 = __expf((s[2 * kf][2] - nm1) * scale);
                float p03 = __expf((s[2 * kf][3] - nm1) * scale);
                float p10 = __expf((s[2 * kf + 1][0] - nm0) * scale);
                float p11 = __expf((s[2 * kf + 1][1] - nm0) * scale);
                float p12 = __expf((s[2 * kf + 1][2] - nm1) * scale);
                float p13 = __expf((s[2 * kf + 1][3] - nm1) * scale);
                ps0 += (p00 + p01) + (p10 + p11);
                ps1 += (p02 + p03) + (p12 + p13);
                pf[kf][0] = packh2(p00, p01);
                pf[kf][1] = packh2(p02, p03);
                pf[kf][2] = packh2(p10, p11);
                pf[kf][3] = packh2(p12, p13);
            }
            sm0 = sm0 * corr0 + ps0;
            sm1 = sm1 * corr1 + ps1;
#pragma unroll
            for (int nt = 0; nt < 4; nt++) {
                o_[nt][0] *= corr0; o_[nt][1] *= corr0;
                o_[nt][2] *= corr1; o_[nt][3] *= corr1;
            }

#pragma unroll
            for (int kf = 0; kf < 4; kf++) {
                int k0 = base + kf * 16;
                uint32_t vrow = (uint32_t)((k0 + (lane & 15)) * 40 + ((lane >> 4) << 3));
                uint32_t vf[4];
                ldsm4t(vf, sb + voff + vrow * 2u);
                HMMA(o_[0], pf[kf], vf[0], vf[1]);
                HMMA(o_[1], pf[kf], vf[2], vf[3]);
                ldsm4t(vf, sb + voff + (vrow + 16u) * 2u);
                HMMA(o_[2], pf[kf], vf[0], vf[1]);
                HMMA(o_[3], pf[kf], vf[2], vf[3]);
            }
        }

        float rs0 = sm0 + __shfl_xor_sync(0xffffffffu, sm0, 1);
        rs0 += __shfl_xor_sync(0xffffffffu, rs0, 2);
        float rs1 = sm1 + __shfl_xor_sync(0xffffffffu, sm1, 1);
        rs1 += __shfl_xor_sync(0xffffffffu, rs1, 2);
        float inv0 = 1.f / rs0, inv1 = 1.f / rs1;
        long r0base = q0row * 256 + h * 32 + 2 * t;
        long r1base = r0base + 8L * 256;
#pragma unroll
        for (int nt = 0; nt < 4; nt++) {
            *(__half2*)(oh + r0base + nt * 8) = __floats2half2_rn(o_[nt][0] * inv0, o_[nt][1] * inv0);
            *(__half2*)(oh + r1base + nt * 8) = __floats2half2_rn(o_[nt][2] * inv1, o_[nt][3] * inv1);
        }
    }

    // ---- fused pad-rep attention for row NN+g using staged smem K/V ----
    __syncthreads();
    for (int m = tid; m < len; m += 128) {
        const __half2* kr = (const __half2*)(smh + m * 40);
        float s = 0.f;
#pragma unroll
        for (int d = 0; d < 16; d++) {
            float2 k2 = __half22float2(kr[d]);
            s = fmaf(qsh[2 * d], k2.x, s);
            s = fmaf(qsh[2 * d + 1], k2.y, s);
        }
        spf[m] = s;
    }
    __syncthreads();
    if (tid < 32) {
        float mx = -3e38f;
        for (int m = tid; m < len; m += 32) mx = fmaxf(mx, spf[m]);
#pragma unroll
        for (int off = 16; off; off >>= 1)
            mx = fmaxf(mx, __shfl_xor_sync(0xffffffffu, mx, off));
        float sm = 0.f;
        for (int m = tid; m < len; m += 32) {
            float p = __expf((spf[m] - mx) * 0.17677669529663687f);
            spf[m] = p;
            sm += p;
        }
#pragma unroll
        for (int off = 16; off; off >>= 1)
            sm += __shfl_xor_sync(0xffffffffu, sm, off);
        if (tid == 0) s_sm = sm;
    }
    __syncthreads();
    int d = tid & 31, wq = tid >> 5;
    float acc = 0.f;
    for (int m = wq; m < len; m += 4)
        acc = fmaf(spf[m], __half2float(smh[320 * 40 + m * 40 + d]), acc);
    av[wq][d] = acc;
    __syncthreads();
    if (tid < 32) {
        float a = ((av[0][tid] + av[1][tid]) + (av[2][tid] + av[3][tid])) / s_sm;
        oh[(long)(NN + g) * 256 + h * 32 + tid] = __float2half(a);
    }
}

// ---------------- host orchestration ----------------------------------------
static void run_hgemm64(const __half* A, const __half* Bt, const float* bias, void* C,
                        int M, int N, int K, int lda, int ldc, int relu, int outh,
                        float* outf) {
    dim3 grid(N / 64, M / 128);
    hgemm64<<<grid, 256, HSMEM64>>>(A, Bt, bias, C, M, N, K, lda, ldc, relu, outh, outf);
}

extern "C" void kernel_launch(void* const* d_in, const int* in_sizes, int n_in,
                              void* d_out, int out_size) {
    const float* x       = (const float*)d_in[0];
    const int*   ei      = (const int*)d_in[1];
    const int*   batches = (const int*)d_in[2];

    int wi = 3;
    if (n_in >= 29 && in_sizes[3] == 1) wi = 4;

    const float* sW0  = (const float*)d_in[wi++];
    const float* sWn0 = (const float*)d_in[wi++];
    const float* sb0  = (const float*)d_in[wi++];
    const float* sW1  = (const float*)d_in[wi++];
    const float* sWn1 = (const float*)d_in[wi++];
    const float* sb1  = (const float*)d_in[wi++];
    const float* sW2  = (const float*)d_in[wi++];
    const float* sWn2 = (const float*)d_in[wi++];
    const float* sb2  = (const float*)d_in[wi++];
    const float* Wq   = (const float*)d_in[wi++];
    const float* Wk   = (const float*)d_in[wi++];
    const float* Wv   = (const float*)d_in[wi++];
    const float* bq   = (const float*)d_in[wi++];
    const float* bk   = (const float*)d_in[wi++];
    const float* bv   = (const float*)d_in[wi++];
    const float* Wo   = (const float*)d_in[wi++];
    const float* bo   = (const float*)d_in[wi++];
    const float* ln1g = (const float*)d_in[wi++];
    const float* ln1b = (const float*)d_in[wi++];
    const float* ln2g = (const float*)d_in[wi++];
    const float* ln2b = (const float*)d_in[wi++];
    const float* W1   = (const float*)d_in[wi++];
    const float* b1   = (const float*)d_in[wi++];
    const float* W2   = (const float*)d_in[wi++];
    const float* b2   = (const float*)d_in[wi++];

    int *rowptr, *cnt, *csrc, *bsum;
    float *comb0, *wsg0, *hp, *bqkv;
    __half *comb1h, *comb2h, *hph, *qkvh, *oh, *midh;
    __half *wsg1t, *wsg2t, *wqkvt, *wot, *w1t, *w2t;
    cudaGetSymbolAddress((void**)&rowptr, g_rowptr);
    cudaGetSymbolAddress((void**)&cnt,    g_cnt);
    cudaGetSymbolAddress((void**)&csrc,   g_csrc);
    cudaGetSymbolAddress((void**)&bsum,   g_bsum);
    cudaGetSymbolAddress((void**)&comb0,  g_comb0);
    cudaGetSymbolAddress((void**)&wsg0,   g_wsg0);
    cudaGetSymbolAddress((void**)&comb1h, g_comb1h);
    cudaGetSymbolAddress((void**)&comb2h, g_comb2h);
    cudaGetSymbolAddress((void**)&hp,     g_hp);
    cudaGetSymbolAddress((void**)&hph,    g_hph);
    cudaGetSymbolAddress((void**)&qkvh,   g_qkvh);
    cudaGetSymbolAddress((void**)&oh,     g_oh);
    cudaGetSymbolAddress((void**)&midh,   g_midh);
    cudaGetSymbolAddress((void**)&wsg1t,  g_wsg1t);
    cudaGetSymbolAddress((void**)&wsg2t,  g_wsg2t);
    cudaGetSymbolAddress((void**)&wqkvt,  g_wqkvt);
    cudaGetSymbolAddress((void**)&wot,    g_wot);
    cudaGetSymbolAddress((void**)&w1t,    g_w1t);
    cudaGetSymbolAddress((void**)&w2t,    g_w2t);
    cudaGetSymbolAddress((void**)&bqkv,   g_bqkv);

    cudaFuncSetAttribute(attn_mma, cudaFuncAttributeMaxDynamicSharedMemorySize, ATT_SMEM);
    cudaFuncSetAttribute(hgemm64, cudaFuncAttributeMaxDynamicSharedMemorySize, HSMEM64);
    cudaFuncSetAttribute(hgemm256, cudaFuncAttributeMaxDynamicSharedMemorySize, HSMEM256);
    cudaFuncSetAttribute(hgemm_ln, cudaFuncAttributeMaxDynamicSharedMemorySize, HSMEM_LN);

    // ---- all weight transposes in one launch ----
    TJobs J;
    const float* srcs[10] = {sW1, sWn1, sW2, sWn2, Wq, Wk, Wv, Wo, W1, W2};
    __half* dsts[10] = {wsg1t, wsg1t + 256, wsg2t, wsg2t + 256,
                        wqkvt, wqkvt + 65536, wqkvt + 131072, wot, w1t, w2t};
    int gxs[10]  = {8, 8, 8, 8, 8, 8, 8, 8, 32, 8};
    int gys[10]  = {8, 8, 8, 8, 8, 8, 8, 8, 8, 32};
    int nzs[10]  = {1, 1, 1, 1, 4, 4, 4, 4, 4, 4};
    int Ns[10]   = {256, 256, 256, 256, 256, 256, 256, 256, 1024, 256};
    int ldds[10] = {512, 512, 512, 512, 256, 256, 256, 256, 256, 1024};
    long slss[10] = {0, 0, 0, 0, 65536, 65536, 65536, 65536, 262144, 262144};
    long dlss[10] = {0, 0, 0, 0, 196608, 196608, 196608, 65536, 262144, 262144};
    int acc = 0;
    for (int i = 0; i < 10; i++) {
        J.src[i] = srcs[i]; J.dst[i] = dsts[i];
        J.gx[i] = gxs[i]; J.gy[i] = gys[i]; J.N[i] = Ns[i]; J.ldd[i] = ldds[i];
        J.sls[i] = slss[i]; J.dls[i] = dlss[i];
        J.base[i] = acc;
        acc += gxs[i] * gys[i] * nzs[i];
    }
    J.base[10] = acc;
    transpose_all<<<acc, dim3(32, 8)>>>(J);
    misc_pack<<<172, 256>>>(hp, hph, oh, sW0, sWn0, wsg0, bq, bk, bv, bqkv);

    // ---- CSR build (parallel 3-phase scan) ----
    cudaMemsetAsync(cnt, 0, NN * sizeof(int), 0);
    degi_kernel<<<(NE + 255) / 256, 256>>>(ei, cnt);
    scan_local<<<NN / 256, 256>>>(cnt, rowptr, bsum);
    scan_bsum<<<1, 32>>>(bsum);
    scan_add<<<NN / 256, 256>>>(rowptr, bsum);
    fill_kernel<<<(NE + 255) / 256, 256>>>(ei, cnt, csrc);

    // ---- SAGE layer 0 ----
    agg0_kernel<<<NN / 8, 256>>>(x, comb0);
    gemm32h_kernel<<<dim3(256 / BN, NN / BM), 256>>>(comb0, wsg0, sb0, comb1h, 512);

    // ---- SAGE layer 1 ----
    agg_csr_h<<<NN, 128>>>(comb1h);
    run_hgemm64(comb1h, wsg1t, sb1, comb2h, NN, 256, 512, 512, 512, 1, 1, nullptr);

    // ---- SAGE layer 2: write compact hp (fp32) + hph (half) directly -------
    agg_csr_h<<<NN, 128>>>(comb2h);
    run_hgemm64(comb2h, wsg2t, sb2, hph, NN, 256, 512, 512, 256, 0, 1, hp);

    // ---- 4 transformer layers on compact rows [0, MTOT) ----
    for (int l = 0; l < 4; l++) {
        hgemm256<<<dim3(768 / 256, MTOT / 128), 256, HSMEM256>>>(
            hph, wqkvt + (long)l * 196608, bqkv + l * 768, qkvh, 256, 256, 768, 0);

        attn_mma<<<dim3(NG, NHD), 128, ATT_SMEM>>>(qkvh, batches, oh);

        hgemm_ln<<<MTOT / 64, 256, HSMEM_LN>>>(
            oh, wot + (long)l * 65536, bo + l * 256, hp,
            ln1g + l * EMBD, ln1b + l * EMBD, hp, hph, 256);

        hgemm256<<<dim3(1024 / 256, MTOT / 128), 256, HSMEM256>>>(
            hph, w1t + (long)l * 262144, b1 + l * FFND, midh, 256, 256, 1024, 1);

        hgemm_ln<<<MTOT / 64, 256, HSMEM_LN>>>(
            midh, w2t + (long)l * 262144, b2 + l * 256, hp,
            ln2g + l * EMBD, ln2b + l * EMBD, hp, (l < 3) ? hph : nullptr, 1024);
    }

    // ---- expand compact -> [LMAX, NG, EMB] with pad broadcast ----
    scatter_out<<<dim3(LMAXC, NG), EMBD>>>(hp, batches, (float*)d_out);
}

// round 16
// speedup vs baseline: 1.0008x; 1.0008x over previous
#include <cuda_runtime.h>
#include <cuda_fp16.h>
#include <math.h>
#include <stdint.h>

#define NN   16384
#define NE   262144
#define NG   64
#define LMAXC 320
#define EMBD 256
#define FFND 1024
#define NHD  8
#define DHD  32
#define NTOK (LMAXC*NG)
#define MTOT 16512            // 16384 nodes + 64 pad reps + 64 zero rows (129*128)

// ---------------- scratch (device globals; no allocation allowed) ----------
__device__ int   g_rowptr[NN + 1];
__device__ int   g_cnt[NN];
__device__ int   g_csrc[NE];
__device__ int   g_bsum[64];
__device__ int   g_tokmap[MTOT];
__device__ float g_comb0[NN*32];
__device__ float g_wsg0[32*256];
__device__ __align__(256) __half g_comb1h[NN*512];
__device__ __align__(256) __half g_comb2h[NN*512];
__device__ float g_hp [MTOT*EMBD];
__device__ __align__(256) __half g_hph[MTOT*EMBD];
__device__ __align__(256) __half g_qkvh[MTOT*768];
__device__ __align__(256) __half g_oh[MTOT*EMBD];
__device__ __align__(256) __half g_midh[MTOT*FFND];
__device__ __align__(256) __half g_wsg1t[256*512];
__device__ __align__(256) __half g_wsg2t[256*512];
__device__ __align__(256) __half g_wqkvt[4*768*256];
__device__ __align__(256) __half g_wot[4*256*256];
__device__ __align__(256) __half g_w1t[4*1024*256];
__device__ __align__(256) __half g_w2t[4*256*1024];
__device__ float g_bqkv[4*768];

// =================== CSR build =============================================
__global__ void degi_kernel(const int* __restrict__ ei, int* __restrict__ cnt) {
    int e = blockIdx.x * blockDim.x + threadIdx.x;
    if (e < NE) atomicAdd(&cnt[ei[NE + e]], 1);
}

__global__ void scan_local(int* __restrict__ cnt, int* __restrict__ rowptr,
                           int* __restrict__ bsum) {
    __shared__ int wsum[8];
    int n = blockIdx.x * 256 + threadIdx.x;
    int lane = threadIdx.x & 31, w = threadIdx.x >> 5;
    int c = cnt[n];
    int inc = c;
#pragma unroll
    for (int off = 1; off < 32; off <<= 1) {
        int v = __shfl_up_sync(0xffffffffu, inc, off);
        if (lane >= off) inc += v;
    }
    if (lane == 31) wsum[w] = inc;
    __syncthreads();
    if (threadIdx.x == 0) {
        int acc = 0;
#pragma unroll
        for (int i = 0; i < 8; i++) { int t = wsum[i]; wsum[i] = acc; acc += t; }
        bsum[blockIdx.x] = acc;
    }
    __syncthreads();
    rowptr[n] = inc - c + wsum[w];
    cnt[n] = 0;
}

__global__ void scan_bsum(int* __restrict__ bsum) {
    int lane = threadIdx.x;
    int a = bsum[lane], b = bsum[lane + 32];
    int inc = a;
#pragma unroll
    for (int off = 1; off < 32; off <<= 1) {
        int v = __shfl_up_sync(0xffffffffu, inc, off);
        if (lane >= off) inc += v;
    }
    int tot0 = __shfl_sync(0xffffffffu, inc, 31);
    int inc2 = b;
#pragma unroll
    for (int off = 1; off < 32; off <<= 1) {
        int v = __shfl_up_sync(0xffffffffu, inc2, off);
        if (lane >= off) inc2 += v;
    }
    bsum[lane] = inc - a;
    bsum[lane + 32] = tot0 + inc2 - b;
}

__global__ void scan_add(int* __restrict__ rowptr, const int* __restrict__ bsum) {
    int n = blockIdx.x * 256 + threadIdx.x;
    rowptr[n] += bsum[blockIdx.x];
    if (n == 0) rowptr[NN] = NE;
}

__global__ void fill_kernel(const int* __restrict__ ei, int* __restrict__ cnt,
                            int* __restrict__ csrc) {
    int e = blockIdx.x * blockDim.x + threadIdx.x;
    if (e >= NE) return;
    int d = ei[NE + e];
    int pos = atomicAdd(&cnt[d], 1);
    csrc[g_rowptr[d] + pos] = ei[e];
}

// compact row -> output token index; pad reps -> first padded slot; -1 = skip
__global__ void tokmap_kernel(const int* __restrict__ batches, int* __restrict__ map) {
    __shared__ int b[65];
    if (threadIdx.x < 65) b[threadIdx.x] = batches[threadIdx.x];
    __syncthreads();
    int n = blockIdx.x * 256 + threadIdx.x;
    if (n >= MTOT) return;
    if (n < NN) {
        int g = 0;
#pragma unroll 8
        for (int i = 1; i < 64; i++) if (b[i] <= n) g = i;
        map[n] = (n - b[g]) * NG + g;
    } else if (n < NN + 64) {
        int g = n - NN;
        int len = b[g + 1] - b[g];
        map[n] = (len < LMAXC) ? len * NG + g : -1;
    } else {
        map[n] = -1;
    }
}

// broadcast first padded slot to remaining padded slots inside d_out
__global__ void pad_fill(const int* __restrict__ batches, float* __restrict__ out) {
    int l = blockIdx.x, g = blockIdx.y;
    int len = batches[g + 1] - batches[g];
    if (l <= len) return;
    out[((long)l * NG + g) * EMBD + threadIdx.x] =
        out[((long)len * NG + g) * EMBD + threadIdx.x];
}

// merged small prologue work: zero tail rows + pack sW0/sWn0 + pack qkv bias
__global__ void misc_pack(float* __restrict__ hp, __half* __restrict__ hph,
                          __half* __restrict__ oh,
                          const float* __restrict__ Ws, const float* __restrict__ Wn,
                          float* __restrict__ w0out,
                          const float* __restrict__ bq, const float* __restrict__ bk,
                          const float* __restrict__ bv, float* __restrict__ bout) {
    int b = blockIdx.x;
    int tid = threadIdx.x;
    if (b < 128) {
        long o = (long)(NN + b) * EMBD + tid;
        hp[o] = 0.0f;
        hph[o] = __float2half(0.0f);
        oh[o] = __float2half(0.0f);
    } else if (b < 160) {
        int k = b - 128;
        w0out[k * 256 + tid] = (k < 16) ? Ws[k * 256 + tid] : Wn[(k - 16) * 256 + tid];
    } else {
        int idx = b - 160;
        int s = idx % 3, l = idx / 3;
        const float* src = (s == 0) ? bq : ((s == 1) ? bk : bv);
        bout[l * 768 + s * 256 + tid] = src[l * 256 + tid];
    }
}

// =================== SAGE layer-0 input assembly ===========================
__global__ void agg0_kernel(const float* __restrict__ x, float* __restrict__ comb0) {
    int w = threadIdx.x >> 5;
    int lane = threadIdx.x & 31;
    int node = blockIdx.x * 8 + w;
    if (lane >= 16) return;
    int s0 = g_rowptr[node], s1 = g_rowptr[node + 1];
    float sum = 0.f;
    for (int j = s0; j < s1; j++) sum += x[g_csrc[j] * 16 + lane];
    comb0[node * 32 + lane] = x[node * 16 + lane];
    comb0[node * 32 + 16 + lane] = sum / fmaxf((float)(s1 - s0), 1.f);
}

__global__ void agg_csr_h(__half* __restrict__ feat) {
    int node = blockIdx.x;
    int c = threadIdx.x;
    const __half2* f2 = (const __half2*)feat;
    int s0 = g_rowptr[node], s1 = g_rowptr[node + 1];
    float sx = 0.f, sy = 0.f;
    int j = s0;
    for (; j + 4 <= s1; j += 4) {
        float2 v0 = __half22float2(f2[(long)g_csrc[j]     * 256 + c]);
        float2 v1 = __half22float2(f2[(long)g_csrc[j + 1] * 256 + c]);
        float2 v2 = __half22float2(f2[(long)g_csrc[j + 2] * 256 + c]);
        float2 v3 = __half22float2(f2[(long)g_csrc[j + 3] * 256 + c]);
        sx += (v0.x + v1.x) + (v2.x + v3.x);
        sy += (v0.y + v1.y) + (v2.y + v3.y);
    }
    for (; j < s1; j++) {
        float2 a = __half22float2(f2[(long)g_csrc[j] * 256 + c]);
        sx += a.x; sy += a.y;
    }
    float inv = 1.f / fmaxf((float)(s1 - s0), 1.f);
    ((__half2*)feat)[(long)node * 256 + 128 + c] = __floats2half2_rn(sx * inv, sy * inv);
}

// ---- all 10 weight transposes (fp32 [K,N] -> half [N,K]) in ONE launch ----
struct TJobs {
    const float* src[10];
    __half*      dst[10];
    int gx[10], gy[10], N[10], ldd[10];
    long sls[10], dls[10];
    int base[11];
};

__global__ void transpose_all(TJobs J) {
    __shared__ float t[32][33];
    int b = blockIdx.x;
    int j = 0;
#pragma unroll
    for (int i = 0; i < 10; i++) if (b >= J.base[i + 1]) j = i + 1;
    int local = b - J.base[j];
    int tpz = J.gx[j] * J.gy[j];
    int z = local / tpz, rem = local - z * tpz;
    int ky = rem / J.gx[j], nx = rem - ky * J.gx[j];
    const float* s = J.src[j] + (long)z * J.sls[j];
    __half* d = J.dst[j] + (long)z * J.dls[j];
    int N = J.N[j], ldd = J.ldd[j];
    int k0 = ky * 32, n0 = nx * 32;
    int tx = threadIdx.x, ty = threadIdx.y;
#pragma unroll
    for (int i = 0; i < 32; i += 8)
        t[ty + i][tx] = s[(long)(k0 + ty + i) * N + n0 + tx];
    __syncthreads();
#pragma unroll
    for (int i = 0; i < 32; i += 8)
        d[(long)(n0 + ty + i) * ldd + k0 + tx] = __float2half(t[tx][ty + i]);
}

// ================= fp32 GEMM K=32 for SAGE layer 0, half output =============
#define BM 64
#define BN 64
__global__ void gemm32h_kernel(const float* __restrict__ A, const float* __restrict__ B,
                               const float* __restrict__ bias, __half* __restrict__ C,
                               int ldc) {
    __shared__ float As[16][BM + 1];
    __shared__ float Bs[16][BN];
    int bm = blockIdx.y * BM;
    int bn = blockIdx.x * BN;
    int tid = threadIdx.x;
    int tx = tid & 15;
    int ty = tid >> 4;
    float r[4][4];
#pragma unroll
    for (int i = 0; i < 4; i++)
#pragma unroll
        for (int j = 0; j < 4; j++) r[i][j] = 0.0f;

    for (int k0 = 0; k0 < 32; k0 += 16) {
#pragma unroll
        for (int i = 0; i < 4; i++) {
            int idx = tid + i * 256;
            int rr = idx >> 4, cc = idx & 15;
            As[cc][rr] = A[(long)(bm + rr) * 32 + k0 + cc];
        }
#pragma unroll
        for (int i = 0; i < 4; i++) {
            int idx = tid + i * 256;
            int rr = idx >> 6, cc = idx & 63;
            Bs[rr][cc] = B[(long)(k0 + rr) * 256 + bn + cc];
        }
        __syncthreads();
#pragma unroll
        for (int kk = 0; kk < 16; kk++) {
            float a[4], b[4];
#pragma unroll
            for (int i = 0; i < 4; i++) a[i] = As[kk][ty * 4 + i];
#pragma unroll
            for (int j = 0; j < 4; j++) b[j] = Bs[kk][tx * 4 + j];
#pragma unroll
            for (int i = 0; i < 4; i++)
#pragma unroll
                for (int j = 0; j < 4; j++) r[i][j] = fmaf(a[i], b[j], r[i][j]);
        }
        __syncthreads();
    }
#pragma unroll
    for (int i = 0; i < 4; i++) {
        long row = bm + ty * 4 + i;
        __half2* C2 = (__half2*)(C + row * ldc + bn + tx * 4);
#pragma unroll
        for (int j = 0; j < 4; j += 2) {
            int col = bn + tx * 4 + j;
            float v0 = fmaxf(r[i][j] + bias[col], 0.f);
            float v1 = fmaxf(r[i][j + 1] + bias[col + 1], 0.f);
            C2[j >> 1] = __floats2half2_rn(v0, v1);
        }
    }
}

// ================= FP16 tensor-core GEMM common helpers ======================
#define HSTR 72
#define HBUF (128*HSTR)
#define HSMEM (4*HBUF*2)

#define CPA16(dst, src) asm volatile("cp.async.cg.shared.global [%0], [%1], 16;" :: "r"(dst), "l"(src))

__device__ __forceinline__ void ldsm4(uint32_t (&r)[4], uint32_t addr) {
    asm volatile("ldmatrix.sync.aligned.m8n8.x4.shared.b16 {%0,%1,%2,%3}, [%4];"
                 : "=r"(r[0]), "=r"(r[1]), "=r"(r[2]), "=r"(r[3]) : "r"(addr));
}
__device__ __forceinline__ void ldsm4t(uint32_t (&r)[4], uint32_t addr) {
    asm volatile("ldmatrix.sync.aligned.m8n8.x4.trans.shared.b16 {%0,%1,%2,%3}, [%4];"
                 : "=r"(r[0]), "=r"(r[1]), "=r"(r[2]), "=r"(r[3]) : "r"(addr));
}

#define HMMA(d, a, b0, b1) asm volatile( \
    "mma.sync.aligned.m16n8k16.row.col.f32.f16.f16.f32 " \
    "{%0,%1,%2,%3}, {%4,%5,%6,%7}, {%8,%9}, {%0,%1,%2,%3};" \
    : "+f"(d[0]), "+f"(d[1]), "+f"(d[2]), "+f"(d[3]) \
    : "r"(a[0]), "r"(a[1]), "r"(a[2]), "r"(a[3]), "r"(b0), "r"(b1))

__device__ __forceinline__ uint32_t packh2(float a, float b) {
    __half2 h = __floats2half2_rn(a, b);
    return *(uint32_t*)&h;
}

// ================= hgemm: 128x128 tile (for N=768/1024 GEMMs) ===============
__global__ void __launch_bounds__(256, 2)
hgemm(const __half* __restrict__ A, const __half* __restrict__ Bt,
      const float* __restrict__ bias, void* __restrict__ Cv,
      int M, int N, int K, int lda, int ldc, int relu, int outh) {
    extern __shared__ __half shh[];
    const int tid  = threadIdx.x;
    const int lane = tid & 31;
    const int wid  = tid >> 5;
    const int wr   = wid >> 2;
    const int wc   = wid & 3;
    const int bm   = blockIdx.y * 128;
    const int bn   = blockIdx.x * 128;

    uint32_t sbase = (uint32_t)__cvta_generic_to_shared(shh);

    float acc[4][4][4];
#pragma unroll
    for (int mt = 0; mt < 4; mt++)
#pragma unroll
        for (int nt = 0; nt < 4; nt++)
#pragma unroll
            for (int r = 0; r < 4; r++) acc[mt][nt][r] = 0.0f;

#define HLOAD(buf, k0)                                                          \
    do {                                                                        \
        _Pragma("unroll")                                                       \
        for (int i = 0; i < 4; i++) {                                           \
            int idx = tid + i * 256;                                            \
            int r = idx >> 3, c = (idx & 7) << 3;                               \
            CPA16(sbase + (uint32_t)((buf) * HBUF + r * HSTR + c) * 2u,         \
                  A + (long)(bm + r) * lda + (k0) + c);                         \
        }                                                                       \
        _Pragma("unroll")                                                       \
        for (int i = 0; i < 4; i++) {                                           \
            int idx = tid + i * 256;                                            \
            int r = idx >> 3, c = (idx & 7) << 3;                               \
            CPA16(sbase + (uint32_t)((2 + (buf)) * HBUF + r * HSTR + c) * 2u,   \
                  Bt + (long)(bn + r) * K + (k0) + c);                          \
        }                                                                       \
        asm volatile("cp.async.commit_group;");                                 \
    } while (0)

    const int nk = K >> 6;
    HLOAD(0, 0);

    const int arow = wr * 64 + (lane & 15);
    const int ach  = (lane >> 4) << 3;
    const int brow16 = wc * 32 + (lane & 15);
    const int bch16  = (lane >> 4) << 3;

    for (int it = 0; it < nk; it++) {
        int cur = it & 1;
        if (it + 1 < nk) {
            HLOAD(cur ^ 1, (it + 1) << 6);
            asm volatile("cp.async.wait_group 1;");
        } else {
            asm volatile("cp.async.wait_group 0;");
        }
        __syncthreads();

        uint32_t aB = sbase + (uint32_t)(cur * HBUF) * 2u;
        uint32_t bB = sbase + (uint32_t)((2 + cur) * HBUF) * 2u;

#pragma unroll
        for (int ks = 0; ks < 4; ks++) {
            uint32_t af[4][4], bf[4][2];
#pragma unroll
            for (int mt = 0; mt < 4; mt++)
                ldsm4(af[mt], aB + (uint32_t)((arow + mt * 16) * HSTR + ks * 16 + ach) * 2u);
#pragma unroll
            for (int np = 0; np < 2; np++) {
                uint32_t br[4];
                ldsm4(br, bB + (uint32_t)((brow16 + np * 16) * HSTR + ks * 16 + bch16) * 2u);
                bf[2 * np][0] = br[0];     bf[2 * np][1] = br[2];
                bf[2 * np + 1][0] = br[1]; bf[2 * np + 1][1] = br[3];
            }
#pragma unroll
            for (int mt = 0; mt < 4; mt++)
#pragma unroll
                for (int nt = 0; nt < 4; nt++)
                    HMMA(acc[mt][nt], af[mt], bf[nt][0], bf[nt][1]);
        }
        __syncthreads();
    }

#pragma unroll
    for (int mt = 0; mt < 4; mt++) {
        int row = bm + wr * 64 + mt * 16 + (lane >> 2);
#pragma unroll
        for (int nt = 0; nt < 4; nt++) {
            int col = bn + wc * 32 + nt * 8 + ((lane & 3) << 1);
            float b0 = bias[col], b1 = bias[col + 1];
            float v0 = acc[mt][nt][0] + b0, v1 = acc[mt][nt][1] + b1;
            float v2 = acc[mt][nt][2] + b0, v3 = acc[mt][nt][3] + b1;
            if (relu) { v0 = fmaxf(v0, 0.f); v1 = fmaxf(v1, 0.f);
                        v2 = fmaxf(v2, 0.f); v3 = fmaxf(v3, 0.f); }
            if (outh) {
                __half2* C2 = (__half2*)Cv;
                C2[((long)row * ldc + col) >> 1]       = __floats2half2_rn(v0, v1);
                C2[((long)(row + 8) * ldc + col) >> 1] = __floats2half2_rn(v2, v3);
            } else {
                float* C = (float*)Cv;
                long i0 = (long)row * ldc + col;
                long i1 = i0 + 8L * ldc;
                C[i0] = v0; C[i0 + 1] = v1; C[i1] = v2; C[i1 + 1] = v3;
            }
        }
    }
#undef HLOAD
}

// ========== hgemm64: 128x64 tile (SAGE layers, N=256) ========================
#define A64BUF (128*HSTR)
#define B64BUF (64*HSTR)
#define HSMEM64 ((2*A64BUF + 2*B64BUF)*2)

__global__ void __launch_bounds__(256, 2)
hgemm64(const __half* __restrict__ A, const __half* __restrict__ Bt,
        const float* __restrict__ bias, void* __restrict__ Cv,
        int M, int N, int K, int lda, int ldc, int relu, int outh,
        float* __restrict__ outf) {
    extern __shared__ __half shh[];
    const int tid  = threadIdx.x;
    const int lane = tid & 31;
    const int wid  = tid >> 5;
    const int wr   = wid >> 1;
    const int wc   = wid & 1;
    const int bm   = blockIdx.y * 128;
    const int bn   = blockIdx.x * 64;

    uint32_t sbase = (uint32_t)__cvta_generic_to_shared(shh);

    float acc[2][4][4];
#pragma unroll
    for (int mt = 0; mt < 2; mt++)
#pragma unroll
        for (int nt = 0; nt < 4; nt++)
#pragma unroll
            for (int r = 0; r < 4; r++) acc[mt][nt][r] = 0.0f;

#define HLOAD64(buf, k0)                                                        \
    do {                                                                        \
        _Pragma("unroll")                                                       \
        for (int i = 0; i < 4; i++) {                                           \
            int idx = tid + i * 256;                                            \
            int r = idx >> 3, c = (idx & 7) << 3;                               \
            CPA16(sbase + (uint32_t)((buf) * A64BUF + r * HSTR + c) * 2u,       \
                  A + (long)(bm + r) * lda + (k0) + c);                         \
        }                                                                       \
        _Pragma("unroll")                                                       \
        for (int i = 0; i < 2; i++) {                                           \
            int idx = tid + i * 256;                                            \
            int r = idx >> 3, c = (idx & 7) << 3;                               \
            CPA16(sbase + (uint32_t)(2 * A64BUF + (buf) * B64BUF + r * HSTR + c) * 2u, \
                  Bt + (long)(bn + r) * K + (k0) + c);                          \
        }                                                                       \
        asm volatile("cp.async.commit_group;");                                 \
    } while (0)

    const int nk = K >> 6;
    HLOAD64(0, 0);

    const int arow = wr * 32 + (lane & 15);
    const int ach  = (lane >> 4) << 3;
    const int brow16 = wc * 32 + (lane & 15);
    const int bch16  = (lane >> 4) << 3;

    for (int it = 0; it < nk; it++) {
        int cur = it & 1;
        if (it + 1 < nk) {
            HLOAD64(cur ^ 1, (it + 1) << 6);
            asm volatile("cp.async.wait_group 1;");
        } else {
            asm volatile("cp.async.wait_group 0;");
        }
        __syncthreads();

        uint32_t aB = sbase + (uint32_t)(cur * A64BUF) * 2u;
        uint32_t bB = sbase + (uint32_t)(2 * A64BUF + cur * B64BUF) * 2u;

#pragma unroll
        for (int ks = 0; ks < 4; ks++) {
            uint32_t af[2][4], bf[4][2];
#pragma unroll
            for (int mt = 0; mt < 2; mt++)
                ldsm4(af[mt], aB + (uint32_t)((arow + mt * 16) * HSTR + ks * 16 + ach) * 2u);
#pragma unroll
            for (int np = 0; np < 2; np++) {
                uint32_t br[4];
                ldsm4(br, bB + (uint32_t)((brow16 + np * 16) * HSTR + ks * 16 + bch16) * 2u);
                bf[2 * np][0] = br[0];     bf[2 * np][1] = br[2];
                bf[2 * np + 1][0] = br[1]; bf[2 * np + 1][1] = br[3];
            }
#pragma unroll
            for (int mt = 0; mt < 2; mt++)
#pragma unroll
                for (int nt = 0; nt < 4; nt++)
                    HMMA(acc[mt][nt], af[mt], bf[nt][0], bf[nt][1]);
        }
        __syncthreads();
    }

#pragma unroll
    for (int mt = 0; mt < 2; mt++) {
        long row = bm + wr * 32 + mt * 16 + (lane >> 2);
#pragma unroll
        for (int nt = 0; nt < 4; nt++) {
            int col = bn + wc * 32 + nt * 8 + ((lane & 3) << 1);
            float b0 = bias[col], b1 = bias[col + 1];
            float v0 = acc[mt][nt][0] + b0, v1 = acc[mt][nt][1] + b1;
            float v2 = acc[mt][nt][2] + b0, v3 = acc[mt][nt][3] + b1;
            if (relu) { v0 = fmaxf(v0, 0.f); v1 = fmaxf(v1, 0.f);
                        v2 = fmaxf(v2, 0.f); v3 = fmaxf(v3, 0.f); }
            if (outf) {
                *(float2*)(outf + row * ldc + col) = make_float2(v0, v1);
                *(float2*)(outf + (row + 8) * ldc + col) = make_float2(v2, v3);
            }
            if (outh) {
                __half2* C2 = (__half2*)Cv;
                C2[(row * ldc + col) >> 1]       = __floats2half2_rn(v0, v1);
                C2[((row + 8) * ldc + col) >> 1] = __floats2half2_rn(v2, v3);
            }
        }
    }
#undef HLOAD64
}

// ===== hgemm_ln: 64x256 tile GEMM + bias + residual + LayerNorm epilogue ====
// If omap != nullptr, fp32 rows are scattered to outf[omap[row]*256+...];
// omap[row] < 0 skips the store (full graphs' reps, filler rows).
#define LNA (64*HSTR)
#define LNB (256*HSTR)
#define HSMEM_LN ((2*LNA + 2*LNB)*2)

__global__ void __launch_bounds__(256, 2)
hgemm_ln(const __half* __restrict__ A, const __half* __restrict__ Bt,
         const float* __restrict__ bias, const float* __restrict__ resid,
         const float* __restrict__ gamma, const float* __restrict__ beta,
         float* __restrict__ outf, __half* __restrict__ outh, int K,
         const int* __restrict__ omap) {
    extern __shared__ __half shh[];
    __shared__ float red[64][4];
    const int tid  = threadIdx.x;
    const int lane = tid & 31;
    const int wid  = tid >> 5;
    const int wr   = wid >> 2;
    const int wc   = wid & 3;
    const long bm  = (long)blockIdx.x * 64;

    uint32_t sbase = (uint32_t)__cvta_generic_to_shared(shh);

    float acc[2][8][4];
#pragma unroll
    for (int mt = 0; mt < 2; mt++)
#pragma unroll
        for (int nt = 0; nt < 8; nt++)
#pragma unroll
            for (int r = 0; r < 4; r++) acc[mt][nt][r] = 0.0f;

#define LNLOAD(buf, k0)                                                         \
    do {                                                                        \
        _Pragma("unroll")                                                       \
        for (int i = 0; i < 2; i++) {                                           \
            int idx = tid + i * 256;                                            \
            int r = idx >> 3, c = (idx & 7) << 3;                               \
            CPA16(sbase + (uint32_t)((buf) * LNA + r * HSTR + c) * 2u,          \
                  A + (bm + r) * K + (k0) + c);                                 \
        }                                                                       \
        _Pragma("unroll")                                                       \
        for (int i = 0; i < 8; i++) {                                           \
            int idx = tid + i * 256;                                            \
            int r = idx >> 3, c = (idx & 7) << 3;                               \
            CPA16(sbase + (uint32_t)(2 * LNA + (buf) * LNB + r * HSTR + c) * 2u,\
                  Bt + (long)r * K + (k0) + c);                                 \
        }                                                                       \
        asm volatile("cp.async.commit_group;");                                 \
    } while (0)

    const int nk = K >> 6;
    LNLOAD(0, 0);

    const int arowb = wr * 32 + (lane & 15);
    const int ach   = (lane >> 4) << 3;
    const int browb = wc * 64 + (lane & 7) + ((lane >> 4) << 3);
    const int bch   = lane & 8;

    for (int it = 0; it < nk; it++) {
        int cur = it & 1;
        if (it + 1 < nk) {
            LNLOAD(cur ^ 1, (it + 1) << 6);
            asm volatile("cp.async.wait_group 1;");
        } else {
            asm volatile("cp.async.wait_group 0;");
        }
        __syncthreads();

        uint32_t aB = sbase + (uint32_t)(cur * LNA) * 2u;
        uint32_t bB = sbase + (uint32_t)(2 * LNA + cur * LNB) * 2u;

#pragma unroll
        for (int ks = 0; ks < 4; ks++) {
            uint32_t af[2][4];
#pragma unroll
            for (int mt = 0; mt < 2; mt++)
                ldsm4(af[mt], aB + (uint32_t)((arowb + mt * 16) * HSTR + ks * 16 + ach) * 2u);
#pragma unroll
            for (int np = 0; np < 4; np++) {
                uint32_t kf[4];
                ldsm4(kf, bB + (uint32_t)((browb + np * 16) * HSTR + ks * 16 + bch) * 2u);
#pragma unroll
                for (int mt = 0; mt < 2; mt++) {
                    HMMA(acc[mt][2 * np],     af[mt], kf[0], kf[1]);
                    HMMA(acc[mt][2 * np + 1], af[mt], kf[2], kf[3]);
                }
            }
        }
        __syncthreads();
    }

    const int q = lane >> 2, t2 = (lane & 3) << 1;
#pragma unroll
    for (int mt = 0; mt < 2; mt++) {
        long r0 = bm + wr * 32 + mt * 16 + q;
        long r1 = r0 + 8;
        float s0 = 0.f, s1 = 0.f;
#pragma unroll
        for (int nt = 0; nt < 8; nt++) {
            int col = wc * 64 + nt * 8 + t2;
            float b0 = bias[col], b1 = bias[col + 1];
            float2 q0 = *(const float2*)(resid + r0 * 256 + col);
            float2 q1 = *(const float2*)(resid + r1 * 256 + col);
            acc[mt][nt][0] += b0 + q0.x; acc[mt][nt][1] += b1 + q0.y;
            acc[mt][nt][2] += b0 + q1.x; acc[mt][nt][3] += b1 + q1.y;
            s0 += acc[mt][nt][0] + acc[mt][nt][1];
            s1 += acc[mt][nt][2] + acc[mt][nt][3];
        }
        s0 += __shfl_xor_sync(0xffffffffu, s0, 1);
        s0 += __shfl_xor_sync(0xffffffffu, s0, 2);
        s1 += __shfl_xor_sync(0xffffffffu, s1, 1);
        s1 += __shfl_xor_sync(0xffffffffu, s1, 2);
        int lr = wr * 32 + mt * 16 + q;
        if ((lane & 3) == 0) { red[lr][wc] = s0; red[lr + 8][wc] = s1; }
    }
    __syncthreads();
    float mean[2][2];
#pragma unroll
    for (int mt = 0; mt < 2; mt++) {
        int lr = wr * 32 + mt * 16 + q;
        mean[mt][0] = (red[lr][0] + red[lr][1] + red[lr][2] + red[lr][3]) * (1.0f / EMBD);
        mean[mt][1] = (red[lr + 8][0] + red[lr + 8][1] + red[lr + 8][2] + red[lr + 8][3]) * (1.0f / EMBD);
    }
    __syncthreads();
#pragma unroll
    for (int mt = 0; mt < 2; mt++) {
        float s0 = 0.f, s1 = 0.f;
#pragma unroll
        for (int nt = 0; nt < 8; nt++) {
            float d0 = acc[mt][nt][0] - mean[mt][0];
            float d1 = acc[mt][nt][1] - mean[mt][0];
            float d2 = acc[mt][nt][2] - mean[mt][1];
            float d3 = acc[mt][nt][3] - mean[mt][1];
            s0 += d0 * d0 + d1 * d1;
            s1 += d2 * d2 + d3 * d3;
        }
        s0 += __shfl_xor_sync(0xffffffffu, s0, 1);
        s0 += __shfl_xor_sync(0xffffffffu, s0, 2);
        s1 += __shfl_xor_sync(0xffffffffu, s1, 1);
        s1 += __shfl_xor_sync(0xffffffffu, s1, 2);
        int lr = wr * 32 + mt * 16 + q;
        if ((lane & 3) == 0) { red[lr][wc] = s0; red[lr + 8][wc] = s1; }
    }
    __syncthreads();
#pragma unroll
    for (int mt = 0; mt < 2; mt++) {
        int lr = wr * 32 + mt * 16 + q;
        float rstd0 = rsqrtf((red[lr][0] + red[lr][1] + red[lr][2] + red[lr][3]) * (1.0f / EMBD) + 1e-5f);
        float rstd1 = rsqrtf((red[lr + 8][0] + red[lr + 8][1] + red[lr + 8][2] + red[lr + 8][3]) * (1.0f / EMBD) + 1e-5f);
        long r0 = bm + lr;
        long r1 = r0 + 8;
        long o0 = r0, o1 = r1;
        if (omap) { o0 = omap[r0]; o1 = omap[r1]; }
#pragma unroll
        for (int nt = 0; nt < 8; nt++) {
            int col = wc * 64 + nt * 8 + t2;
            float g0 = gamma[col], g1 = gamma[col + 1];
            float e0 = beta[col],  e1 = beta[col + 1];
            float v0 = (acc[mt][nt][0] - mean[mt][0]) * rstd0 * g0 + e0;
            float v1 = (acc[mt][nt][1] - mean[mt][0]) * rstd0 * g1 + e1;
            float v2 = (acc[mt][nt][2] - mean[mt][1]) * rstd1 * g0 + e0;
            float v3 = (acc[mt][nt][3] - mean[mt][1]) * rstd1 * g1 + e1;
            if (o0 >= 0) *(float2*)(outf + o0 * 256 + col) = make_float2(v0, v1);
            if (o1 >= 0) *(float2*)(outf + o1 * 256 + col) = make_float2(v2, v3);
            if (outh) {
                *(__half2*)(outh + r0 * 256 + col) = __floats2half2_rn(v0, v1);
                *(__half2*)(outh + r1 * 256 + col) = __floats2half2_rn(v2, v3);
            }
        }
    }
#undef LNLOAD
}

// ============ compact flash attention + fused pad-rep: block per (g, h) =====
#define ATT_SMEM (2*320*40*2 + 320*4)

__global__ void __launch_bounds__(128, 4)
attn_mma(const __half* __restrict__ qkv, const int* __restrict__ batches,
         __half* __restrict__ oh) {
    int g = blockIdx.x, h = blockIdx.y;
    int st = batches[g];
    int len = batches[g + 1] - st;
    extern __shared__ __half smh[];
    uint32_t sb = (uint32_t)__cvta_generic_to_shared(smh);
    const uint32_t voff = 320u * 40u * 2u;
    float* spf = (float*)(smh + 2 * 320 * 40);
    __shared__ float qsh[DHD];
    __shared__ float s_sm;
    __shared__ float av[4][DHD];

    int tid = threadIdx.x;
    for (int idx = tid; idx < len * 4; idx += 128) {
        int l = idx >> 2, c = idx & 3;
        const __half* srcK = qkv + (long)(st + l) * 768 + 256 + h * 32 + c * 8;
        uint32_t d = (uint32_t)(l * 40 + c * 8) * 2u;
        CPA16(sb + d, srcK);
        CPA16(sb + voff + d, srcK + 256);
    }
    asm volatile("cp.async.commit_group;");
    if (tid < DHD)
        qsh[tid] = __half2float(qkv[(long)(NN + g) * 768 + h * 32 + tid]);
    asm volatile("cp.async.wait_group 0;");
    __syncthreads();

    const int w = tid >> 5, lane = tid & 31;
    const int r = lane >> 2, t = lane & 3;
    const int nch = len >> 6;
    const int ntiles = len >> 4;
    const float scale = 0.17677669529663687f;

    for (int mt = w; mt < ntiles; mt += 4) {
        long q0row = (long)(st + mt * 16 + r);
        uint32_t qf[2][4];
        {
            const __half* q0 = qkv + q0row * 768 + h * 32;
            const __half* q1 = q0 + 8L * 768;
#pragma unroll
            for (int ks = 0; ks < 2; ks++) {
                int c0 = ks * 16 + 2 * t;
                qf[ks][0] = *(const uint32_t*)(q0 + c0);
                qf[ks][1] = *(const uint32_t*)(q1 + c0);
                qf[ks][2] = *(const uint32_t*)(q0 + c0 + 8);
                qf[ks][3] = *(const uint32_t*)(q1 + c0 + 8);
            }
        }
        float o_[4][4];
#pragma unroll
        for (int nt = 0; nt < 4; nt++)
#pragma unroll
            for (int j = 0; j < 4; j++) o_[nt][j] = 0.f;
        float mx0 = -3e38f, mx1 = -3e38f, sm0 = 0.f, sm1 = 0.f;

        for (int ch = 0; ch < nch; ch++) {
            int base = ch << 6;
            float s[8][4];
#pragma unroll
            for (int nt = 0; nt < 8; nt++)
#pragma unroll
                for (int j = 0; j < 4; j++) s[nt][j] = 0.f;

#pragma unroll
            for (int ks = 0; ks < 2; ks++) {
#pragma unroll
                for (int np = 0; np < 4; np++) {
                    uint32_t kf[4];
                    int krow = base + np * 16 + (lane & 7) + ((lane >> 4) << 3);
                    int kcol = ks * 16 + (lane & 8);
                    ldsm4(kf, sb + (uint32_t)(krow * 40 + kcol) * 2u);
                    HMMA(s[2 * np],     qf[ks], kf[0], kf[1]);
                    HMMA(s[2 * np + 1], qf[ks], kf[2], kf[3]);
                }
            }

            float cm0 = -3e38f, cm1 = -3e38f;
#pragma unroll
            for (int nt = 0; nt < 8; nt++) {
                cm0 = fmaxf(cm0, fmaxf(s[nt][0], s[nt][1]));
                cm1 = fmaxf(cm1, fmaxf(s[nt][2], s[nt][3]));
            }
            cm0 = fmaxf(cm0, __shfl_xor_sync(0xffffffffu, cm0, 1));
            cm0 = fmaxf(cm0, __shfl_xor_sync(0xffffffffu, cm0, 2));
            cm1 = fmaxf(cm1, __shfl_xor_sync(0xffffffffu, cm1, 1));
            cm1 = fmaxf(cm1, __shfl_xor_sync(0xffffffffu, cm1, 2));
            float nm0 = fmaxf(mx0, cm0), nm1 = fmaxf(mx1, cm1);
            float corr0 = __expf((mx0 - nm0) * scale);
            float corr1 = __expf((mx1 - nm1) * scale);
            mx0 = nm0; mx1 = nm1;

            uint32_t pf[4][4];
            float ps0 = 0.f, ps1 = 0.f;
#pragma unroll
            for (int kf = 0; kf < 4; kf++) {
                float p00 = __expf((s[2 * kf][0] - nm0) * scale);
                float p01 = __expf((s[2 * kf][1] - nm0) * scale);
                float p02 = __expf((s[2 * kf][2] - nm1) * scale);
                float p03 = __expf((s[2 * kf][3] - nm1) * scale);
                float p10 = __expf((s[2 * kf + 1][0] - nm0) * scale);
                float p11 = __expf((s[2 * kf + 1][1] - nm0) * scale);
                float p12 = __expf((s[2 * kf + 1][2] - nm1) * scale);
                float p13 = __expf((s[2 * kf + 1][3] - nm1) * scale);
                ps0 += (p00 + p01) + (p10 + p11);
                ps1 += (p02 + p03) + (p12 + p13);
                pf[kf][0] = packh2(p00, p01);
                pf[kf][1] = packh2(p02, p03);
                pf[kf][2] = packh2(p10, p11);
                pf[kf][3] = packh2(p12, p13);
            }
            sm0 = sm0 * corr0 + ps0;
            sm1 = sm1 * corr1 + ps1;
#pragma unroll
            for (int nt = 0; nt < 4; nt++) {
                o_[nt][0] *= corr0; o_[nt][1] *= corr0;
                o_[nt][2] *= corr1; o_[nt][3] *= corr1;
            }

#pragma unroll
            for (int kf = 0; kf < 4; kf++) {
                int k0 = base + kf * 16;
                uint32_t vrow = (uint32_t)((k0 + (lane & 15)) * 40 + ((lane >> 4) << 3));
                uint32_t vf[4];
                ldsm4t(vf, sb + voff + vrow * 2u);
                HMMA(o_[0], pf[kf], vf[0], vf[1]);
                HMMA(o_[1], pf[kf], vf[2], vf[3]);
                ldsm4t(vf, sb + voff + (vrow + 16u) * 2u);
                HMMA(o_[2], pf[kf], vf[0], vf[1]);
                HMMA(o_[3], pf[kf], vf[2], vf[3]);
            }
        }

        float rs0 = sm0 + __shfl_xor_sync(0xffffffffu, sm0, 1);
        rs0 += __shfl_xor_sync(0xffffffffu, rs0, 2);
        float rs1 = sm1 + __shfl_xor_sync(0xffffffffu, sm1, 1);
        rs1 += __shfl_xor_sync(0xffffffffu, rs1, 2);
        float inv0 = 1.f / rs0, inv1 = 1.f / rs1;
        long r0base = q0row * 256 + h * 32 + 2 * t;
        long r1base = r0base + 8L * 256;
#pragma unroll
        for (int nt = 0; nt < 4; nt++) {
            *(__half2*)(oh + r0base + nt * 8) = __floats2half2_rn(o_[nt][0] * inv0, o_[nt][1] * inv0);
            *(__half2*)(oh + r1base + nt * 8) = __floats2half2_rn(o_[nt][2] * inv1, o_[nt][3] * inv1);
        }
    }

    // ---- fused pad-rep attention for row NN+g using staged smem K/V ----
    __syncthreads();
    for (int m = tid; m < len; m += 128) {
        const __half2* kr = (const __half2*)(smh + m * 40);
        float s = 0.f;
#pragma unroll
        for (int d = 0; d < 16; d++) {
            float2 k2 = __half22float2(kr[d]);
            s = fmaf(qsh[2 * d], k2.x, s);
            s = fmaf(qsh[2 * d + 1], k2.y, s);
        }
        spf[m] = s;
    }
    __syncthreads();
    if (tid < 32) {
        float mx = -3e38f;
        for (int m = tid; m < len; m += 32) mx = fmaxf(mx, spf[m]);
#pragma unroll
        for (int off = 16; off; off >>= 1)
            mx = fmaxf(mx, __shfl_xor_sync(0xffffffffu, mx, off));
        float sm = 0.f;
        for (int m = tid; m < len; m += 32) {
            float p = __expf((spf[m] - mx) * 0.17677669529663687f);
            spf[m] = p;
            sm += p;
        }
#pragma unroll
        for (int off = 16; off; off >>= 1)
            sm += __shfl_xor_sync(0xffffffffu, sm, off);
        if (tid == 0) s_sm = sm;
    }
    __syncthreads();
    int d = tid & 31, wq = tid >> 5;
    float acc = 0.f;
    for (int m = wq; m < len; m += 4)
        acc = fmaf(spf[m], __half2float(smh[320 * 40 + m * 40 + d]), acc);
    av[wq][d] = acc;
    __syncthreads();
    if (tid < 32) {
        float a = ((av[0][tid] + av[1][tid]) + (av[2][tid] + av[3][tid])) / s_sm;
        oh[(long)(NN + g) * 256 + h * 32 + tid] = __float2half(a);
    }
}

// ---------------- host orchestration ----------------------------------------
static void run_hgemm(const __half* A, const __half* Bt, const float* bias, void* C,
                      int M, int N, int K, int lda, int ldc, int relu, int outh) {
    dim3 grid(N / 128, M / 128);
    hgemm<<<grid, 256, HSMEM>>>(A, Bt, bias, C, M, N, K, lda, ldc, relu, outh);
}

static void run_hgemm64(const __half* A, const __half* Bt, const float* bias, void* C,
                        int M, int N, int K, int lda, int ldc, int relu, int outh,
                        float* outf) {
    dim3 grid(N / 64, M / 128);
    hgemm64<<<grid, 256, HSMEM64>>>(A, Bt, bias, C, M, N, K, lda, ldc, relu, outh, outf);
}

extern "C" void kernel_launch(void* const* d_in, const int* in_sizes, int n_in,
                              void* d_out, int out_size) {
    const float* x       = (const float*)d_in[0];
    const int*   ei      = (const int*)d_in[1];
    const int*   batches = (const int*)d_in[2];

    int wi = 3;
    if (n_in >= 29 && in_sizes[3] == 1) wi = 4;

    const float* sW0  = (const float*)d_in[wi++];
    const float* sWn0 = (const float*)d_in[wi++];
    const float* sb0  = (const float*)d_in[wi++];
    const float* sW1  = (const float*)d_in[wi++];
    const float* sWn1 = (const float*)d_in[wi++];
    const float* sb1  = (const float*)d_in[wi++];
    const float* sW2  = (const float*)d_in[wi++];
    const float* sWn2 = (const float*)d_in[wi++];
    const float* sb2  = (const float*)d_in[wi++];
    const float* Wq   = (const float*)d_in[wi++];
    const float* Wk   = (const float*)d_in[wi++];
    const float* Wv   = (const float*)d_in[wi++];
    const float* bq   = (const float*)d_in[wi++];
    const float* bk   = (const float*)d_in[wi++];
    const float* bv   = (const float*)d_in[wi++];
    const float* Wo   = (const float*)d_in[wi++];
    const float* bo   = (const float*)d_in[wi++];
    const float* ln1g = (const float*)d_in[wi++];
    const float* ln1b = (const float*)d_in[wi++];
    const float* ln2g = (const float*)d_in[wi++];
    const float* ln2b = (const float*)d_in[wi++];
    const float* W1   = (const float*)d_in[wi++];
    const float* b1   = (const float*)d_in[wi++];
    const float* W2   = (const float*)d_in[wi++];
    const float* b2   = (const float*)d_in[wi++];

    int *rowptr, *cnt, *csrc, *bsum, *tokmap;
    float *comb0, *wsg0, *hp, *bqkv;
    __half *comb1h, *comb2h, *hph, *qkvh, *oh, *midh;
    __half *wsg1t, *wsg2t, *wqkvt, *wot, *w1t, *w2t;
    cudaGetSymbolAddress((void**)&rowptr, g_rowptr);
    cudaGetSymbolAddress((void**)&cnt,    g_cnt);
    cudaGetSymbolAddress((void**)&csrc,   g_csrc);
    cudaGetSymbolAddress((void**)&bsum,   g_bsum);
    cudaGetSymbolAddress((void**)&tokmap, g_tokmap);
    cudaGetSymbolAddress((void**)&comb0,  g_comb0);
    cudaGetSymbolAddress((void**)&wsg0,   g_wsg0);
    cudaGetSymbolAddress((void**)&comb1h, g_comb1h);
    cudaGetSymbolAddress((void**)&comb2h, g_comb2h);
    cudaGetSymbolAddress((void**)&hp,     g_hp);
    cudaGetSymbolAddress((void**)&hph,    g_hph);
    cudaGetSymbolAddress((void**)&qkvh,   g_qkvh);
    cudaGetSymbolAddress((void**)&oh,     g_oh);
    cudaGetSymbolAddress((void**)&midh,   g_midh);
    cudaGetSymbolAddress((void**)&wsg1t,  g_wsg1t);
    cudaGetSymbolAddress((void**)&wsg2t,  g_wsg2t);
    cudaGetSymbolAddress((void**)&wqkvt,  g_wqkvt);
    cudaGetSymbolAddress((void**)&wot,    g_wot);
    cudaGetSymbolAddress((void**)&w1t,    g_w1t);
    cudaGetSymbolAddress((void**)&w2t,    g_w2t);
    cudaGetSymbolAddress((void**)&bqkv,   g_bqkv);

    cudaFuncSetAttribute(attn_mma, cudaFuncAttributeMaxDynamicSharedMemorySize, ATT_SMEM);
    cudaFuncSetAttribute(hgemm, cudaFuncAttributeMaxDynamicSharedMemorySize, HSMEM);
    cudaFuncSetAttribute(hgemm64, cudaFuncAttributeMaxDynamicSharedMemorySize, HSMEM64);
    cudaFuncSetAttribute(hgemm_ln, cudaFuncAttributeMaxDynamicSharedMemorySize, HSMEM_LN);

    // ---- all weight transposes in one launch ----
    TJobs J;
    const float* srcs[10] = {sW1, sWn1, sW2, sWn2, Wq, Wk, Wv, Wo, W1, W2};
    __half* dsts[10] = {wsg1t, wsg1t + 256, wsg2t, wsg2t + 256,
                        wqkvt, wqkvt + 65536, wqkvt + 131072, wot, w1t, w2t};
    int gxs[10]  = {8, 8, 8, 8, 8, 8, 8, 8, 32, 8};
    int gys[10]  = {8, 8, 8, 8, 8, 8, 8, 8, 8, 32};
    int nzs[10]  = {1, 1, 1, 1, 4, 4, 4, 4, 4, 4};
    int Ns[10]   = {256, 256, 256, 256, 256, 256, 256, 256, 1024, 256};
    int ldds[10] = {512, 512, 512, 512, 256, 256, 256, 256, 256, 1024};
    long slss[10] = {0, 0, 0, 0, 65536, 65536, 65536, 65536, 262144, 262144};
    long dlss[10] = {0, 0, 0, 0, 196608, 196608, 196608, 65536, 262144, 262144};
    int acc = 0;
    for (int i = 0; i < 10; i++) {
        J.src[i] = srcs[i]; J.dst[i] = dsts[i];
        J.gx[i] = gxs[i]; J.gy[i] = gys[i]; J.N[i] = Ns[i]; J.ldd[i] = ldds[i];
        J.sls[i] = slss[i]; J.dls[i] = dlss[i];
        J.base[i] = acc;
        acc += gxs[i] * gys[i] * nzs[i];
    }
    J.base[10] = acc;
    transpose_all<<<acc, dim3(32, 8)>>>(J);
    misc_pack<<<172, 256>>>(hp, hph, oh, sW0, sWn0, wsg0, bq, bk, bv, bqkv);
    tokmap_kernel<<<(MTOT + 255) / 256, 256>>>(batches, tokmap);

    // ---- CSR build (parallel 3-phase scan) ----
    cudaMemsetAsync(cnt, 0, NN * sizeof(int), 0);
    degi_kernel<<<(NE + 255) / 256, 256>>>(ei, cnt);
    scan_local<<<NN / 256, 256>>>(cnt, rowptr, bsum);
    scan_bsum<<<1, 32>>>(bsum);
    scan_add<<<NN / 256, 256>>>(rowptr, bsum);
    fill_kernel<<<(NE + 255) / 256, 256>>>(ei, cnt, csrc);

    // ---- SAGE layer 0 ----
    agg0_kernel<<<NN / 8, 256>>>(x, comb0);
    gemm32h_kernel<<<dim3(256 / BN, NN / BM), 256>>>(comb0, wsg0, sb0, comb1h, 512);

    // ---- SAGE layer 1 ----
    agg_csr_h<<<NN, 128>>>(comb1h);
    run_hgemm64(comb1h, wsg1t, sb1, comb2h, NN, 256, 512, 512, 512, 1, 1, nullptr);

    // ---- SAGE layer 2: write compact hp (fp32) + hph (half) directly -------
    agg_csr_h<<<NN, 128>>>(comb2h);
    run_hgemm64(comb2h, wsg2t, sb2, hph, NN, 256, 512, 512, 256, 0, 1, hp);

    // ---- 4 transformer layers on compact rows [0, MTOT) ----
    for (int l = 0; l < 4; l++) {
        run_hgemm(hph, wqkvt + (long)l * 196608, bqkv + l * 768, qkvh,
                  MTOT, 768, 256, 256, 768, 0, 1);

        attn_mma<<<dim3(NG, NHD), 128, ATT_SMEM>>>(qkvh, batches, oh);

        hgemm_ln<<<MTOT / 64, 256, HSMEM_LN>>>(
            oh, wot + (long)l * 65536, bo + l * 256, hp,
            ln1g + l * EMBD, ln1b + l * EMBD, hp, hph, 256, nullptr);

        run_hgemm(hph, w1t + (long)l * 262144, b1 + l * FFND, midh,
                  MTOT, 1024, 256, 256, 1024, 1, 1);

        if (l < 3) {
            hgemm_ln<<<MTOT / 64, 256, HSMEM_LN>>>(
                midh, w2t + (long)l * 262144, b2 + l * 256, hp,
                ln2g + l * EMBD, ln2b + l * EMBD, hp, hph, 1024, nullptr);
        } else {
            // final layer: scatter LN output straight to d_out via tokmap
            hgemm_ln<<<MTOT / 64, 256, HSMEM_LN>>>(
                midh, w2t + (long)l * 262144, b2 + l * 256, hp,
                ln2g + l * EMBD, ln2b + l * EMBD, (float*)d_out, nullptr, 1024, tokmap);
        }
    }

    // ---- broadcast pad-rep rows to remaining padded output slots ----
    pad_fill<<<dim3(LMAXC, NG), EMBD>>>(batches, (float*)d_out);
}

// round 17
// speedup vs baseline: 1.0105x; 1.0096x over previous
#include <cuda_runtime.h>
#include <cuda_fp16.h>
#include <math.h>
#include <stdint.h>

#define NN   16384
#define NE   262144
#define NG   64
#define LMAXC 320
#define EMBD 256
#define FFND 1024
#define NHD  8
#define DHD  32
#define NTOK (LMAXC*NG)
#define MTOT 16512            // 16384 nodes + 64 pad reps + 64 zero rows (129*128)

// ---------------- scratch (device globals; no allocation allowed) ----------
__device__ int   g_rowptr[NN + 1];
__device__ int   g_cnt[NN];
__device__ int   g_csrc[NE];
__device__ int   g_bsum[64];
__device__ float g_comb0[NN*32];
__device__ float g_wsg0[32*256];
__device__ __align__(256) __half g_comb1h[NN*512];
__device__ __align__(256) __half g_comb2h[NN*512];
__device__ float g_hp [MTOT*EMBD];
__device__ __align__(256) __half g_hph[MTOT*EMBD];
__device__ __align__(256) __half g_qkvh[MTOT*768];
__device__ __align__(256) __half g_oh[MTOT*EMBD];
__device__ __align__(256) __half g_midh[MTOT*FFND];
__device__ __align__(256) __half g_wsg1t[256*512];
__device__ __align__(256) __half g_wsg2t[256*512];
__device__ __align__(256) __half g_wqkvt[4*768*256];
__device__ __align__(256) __half g_wot[4*256*256];
__device__ __align__(256) __half g_w1t[4*1024*256];
__device__ __align__(256) __half g_w2t[4*256*1024];
__device__ float g_bqkv[4*768];

// =================== CSR build =============================================
__global__ void degi_kernel(const int* __restrict__ ei, int* __restrict__ cnt) {
    int e = blockIdx.x * blockDim.x + threadIdx.x;
    if (e < NE) atomicAdd(&cnt[ei[NE + e]], 1);
}

// phase 1: per-block (256-wide) exclusive scan; local prefix -> rowptr,
// block total -> bsum, zero cnt (fill reuses it as a cursor).
__global__ void scan_local(int* __restrict__ cnt, int* __restrict__ rowptr,
                           int* __restrict__ bsum) {
    __shared__ int wsum[8];
    int n = blockIdx.x * 256 + threadIdx.x;
    int lane = threadIdx.x & 31, w = threadIdx.x >> 5;
    int c = cnt[n];
    int inc = c;
#pragma unroll
    for (int off = 1; off < 32; off <<= 1) {
        int v = __shfl_up_sync(0xffffffffu, inc, off);
        if (lane >= off) inc += v;
    }
    if (lane == 31) wsum[w] = inc;
    __syncthreads();
    if (threadIdx.x == 0) {
        int acc = 0;
#pragma unroll
        for (int i = 0; i < 8; i++) { int t = wsum[i]; wsum[i] = acc; acc += t; }
        bsum[blockIdx.x] = acc;
    }
    __syncthreads();
    rowptr[n] = inc - c + wsum[w];
    cnt[n] = 0;
}

// phase 2: exclusive scan of 64 block sums (one warp, 2 elems/lane)
__global__ void scan_bsum(int* __restrict__ bsum) {
    int lane = threadIdx.x;
    int a = bsum[lane], b = bsum[lane + 32];
    int inc = a;
#pragma unroll
    for (int off = 1; off < 32; off <<= 1) {
        int v = __shfl_up_sync(0xffffffffu, inc, off);
        if (lane >= off) inc += v;
    }
    int tot0 = __shfl_sync(0xffffffffu, inc, 31);
    int inc2 = b;
#pragma unroll
    for (int off = 1; off < 32; off <<= 1) {
        int v = __shfl_up_sync(0xffffffffu, inc2, off);
        if (lane >= off) inc2 += v;
    }
    bsum[lane] = inc - a;
    bsum[lane + 32] = tot0 + inc2 - b;
}

// phase 3: add block offsets; rowptr[NN] = NE (constant total)
__global__ void scan_add(int* __restrict__ rowptr, const int* __restrict__ bsum) {
    int n = blockIdx.x * 256 + threadIdx.x;
    rowptr[n] += bsum[blockIdx.x];
    if (n == 0) rowptr[NN] = NE;
}

__global__ void fill_kernel(const int* __restrict__ ei, int* __restrict__ cnt,
                            int* __restrict__ csrc) {
    int e = blockIdx.x * blockDim.x + threadIdx.x;
    if (e >= NE) return;
    int d = ei[NE + e];
    int pos = atomicAdd(&cnt[d], 1);
    csrc[g_rowptr[d] + pos] = ei[e];
}

// merged small prologue work: zero tail rows + pack sW0/sWn0 + pack qkv bias
__global__ void misc_pack(float* __restrict__ hp, __half* __restrict__ hph,
                          __half* __restrict__ oh,
                          const float* __restrict__ Ws, const float* __restrict__ Wn,
                          float* __restrict__ w0out,
                          const float* __restrict__ bq, const float* __restrict__ bk,
                          const float* __restrict__ bv, float* __restrict__ bout) {
    int b = blockIdx.x;
    int tid = threadIdx.x;
    if (b < 128) {
        long o = (long)(NN + b) * EMBD + tid;
        hp[o] = 0.0f;
        hph[o] = __float2half(0.0f);
        oh[o] = __float2half(0.0f);
    } else if (b < 160) {
        int k = b - 128;
        w0out[k * 256 + tid] = (k < 16) ? Ws[k * 256 + tid] : Wn[(k - 16) * 256 + tid];
    } else {
        int idx = b - 160;
        int s = idx % 3, l = idx / 3;
        const float* src = (s == 0) ? bq : ((s == 1) ? bk : bv);
        bout[l * 768 + s * 256 + tid] = src[l * 256 + tid];
    }
}

// expand compact hp -> d_out [LMAX, NG, EMB]; padded positions from rep rows
__global__ void scatter_out(const float* __restrict__ hp, const int* __restrict__ batches,
                            float* __restrict__ out) {
    int l = blockIdx.x, g = blockIdx.y;
    int st = batches[g];
    int len = batches[g + 1] - st;
    long src = (l < len) ? (long)(st + l) : (long)(NN + g);
    out[((long)l * NG + g) * EMBD + threadIdx.x] = hp[src * EMBD + threadIdx.x];
}

// =================== SAGE layer-0 input assembly ===========================
// Also re-zeroes cnt (used as fill cursor) so the next graph replay starts
// from zero without a separate memset launch.
__global__ void agg0_kernel(const float* __restrict__ x, float* __restrict__ comb0,
                            int* __restrict__ cnt) {
    int w = threadIdx.x >> 5;
    int lane = threadIdx.x & 31;
    int node = blockIdx.x * 8 + w;
    if (lane == 0) cnt[node] = 0;
    if (lane >= 16) return;
    int s0 = g_rowptr[node], s1 = g_rowptr[node + 1];
    float sum = 0.f;
    for (int j = s0; j < s1; j++) sum += x[g_csrc[j] * 16 + lane];
    comb0[node * 32 + lane] = x[node * 16 + lane];
    comb0[node * 32 + 16 + lane] = sum / fmaxf((float)(s1 - s0), 1.f);
}

__global__ void agg_csr_h(__half* __restrict__ feat) {
    int node = blockIdx.x;
    int c = threadIdx.x;
    const __half2* f2 = (const __half2*)feat;
    int s0 = g_rowptr[node], s1 = g_rowptr[node + 1];
    float sx = 0.f, sy = 0.f;
    int j = s0;
    for (; j + 4 <= s1; j += 4) {
        float2 v0 = __half22float2(f2[(long)g_csrc[j]     * 256 + c]);
        float2 v1 = __half22float2(f2[(long)g_csrc[j + 1] * 256 + c]);
        float2 v2 = __half22float2(f2[(long)g_csrc[j + 2] * 256 + c]);
        float2 v3 = __half22float2(f2[(long)g_csrc[j + 3] * 256 + c]);
        sx += (v0.x + v1.x) + (v2.x + v3.x);
        sy += (v0.y + v1.y) + (v2.y + v3.y);
    }
    for (; j < s1; j++) {
        float2 a = __half22float2(f2[(long)g_csrc[j] * 256 + c]);
        sx += a.x; sy += a.y;
    }
    float inv = 1.f / fmaxf((float)(s1 - s0), 1.f);
    ((__half2*)feat)[(long)node * 256 + 128 + c] = __floats2half2_rn(sx * inv, sy * inv);
}

// ---- all 10 weight transposes (fp32 [K,N] -> half [N,K]) in ONE launch ----
struct TJobs {
    const float* src[10];
    __half*      dst[10];
    int gx[10], gy[10], N[10], ldd[10];
    long sls[10], dls[10];
    int base[11];
};

__global__ void transpose_all(TJobs J) {
    __shared__ float t[32][33];
    int b = blockIdx.x;
    int j = 0;
#pragma unroll
    for (int i = 0; i < 10; i++) if (b >= J.base[i + 1]) j = i + 1;
    int local = b - J.base[j];
    int tpz = J.gx[j] * J.gy[j];
    int z = local / tpz, rem = local - z * tpz;
    int ky = rem / J.gx[j], nx = rem - ky * J.gx[j];
    const float* s = J.src[j] + (long)z * J.sls[j];
    __half* d = J.dst[j] + (long)z * J.dls[j];
    int N = J.N[j], ldd = J.ldd[j];
    int k0 = ky * 32, n0 = nx * 32;
    int tx = threadIdx.x, ty = threadIdx.y;
#pragma unroll
    for (int i = 0; i < 32; i += 8)
        t[ty + i][tx] = s[(long)(k0 + ty + i) * N + n0 + tx];
    __syncthreads();
#pragma unroll
    for (int i = 0; i < 32; i += 8)
        d[(long)(n0 + ty + i) * ldd + k0 + tx] = __float2half(t[tx][ty + i]);
}

// ================= fp32 GEMM K=32 for SAGE layer 0, half output =============
#define BM 64
#define BN 64
__global__ void gemm32h_kernel(const float* __restrict__ A, const float* __restrict__ B,
                               const float* __restrict__ bias, __half* __restrict__ C,
                               int ldc) {
    __shared__ float As[16][BM + 1];
    __shared__ float Bs[16][BN];
    int bm = blockIdx.y * BM;
    int bn = blockIdx.x * BN;
    int tid = threadIdx.x;
    int tx = tid & 15;
    int ty = tid >> 4;
    float r[4][4];
#pragma unroll
    for (int i = 0; i < 4; i++)
#pragma unroll
        for (int j = 0; j < 4; j++) r[i][j] = 0.0f;

    for (int k0 = 0; k0 < 32; k0 += 16) {
#pragma unroll
        for (int i = 0; i < 4; i++) {
            int idx = tid + i * 256;
            int rr = idx >> 4, cc = idx & 15;
            As[cc][rr] = A[(long)(bm + rr) * 32 + k0 + cc];
        }
#pragma unroll
        for (int i = 0; i < 4; i++) {
            int idx = tid + i * 256;
            int rr = idx >> 6, cc = idx & 63;
            Bs[rr][cc] = B[(long)(k0 + rr) * 256 + bn + cc];
        }
        __syncthreads();
#pragma unroll
        for (int kk = 0; kk < 16; kk++) {
            float a[4], b[4];
#pragma unroll
            for (int i = 0; i < 4; i++) a[i] = As[kk][ty * 4 + i];
#pragma unroll
            for (int j = 0; j < 4; j++) b[j] = Bs[kk][tx * 4 + j];
#pragma unroll
            for (int i = 0; i < 4; i++)
#pragma unroll
                for (int j = 0; j < 4; j++) r[i][j] = fmaf(a[i], b[j], r[i][j]);
        }
        __syncthreads();
    }
#pragma unroll
    for (int i = 0; i < 4; i++) {
        long row = bm + ty * 4 + i;
        __half2* C2 = (__half2*)(C + row * ldc + bn + tx * 4);
#pragma unroll
        for (int j = 0; j < 4; j += 2) {
            int col = bn + tx * 4 + j;
            float v0 = fmaxf(r[i][j] + bias[col], 0.f);
            float v1 = fmaxf(r[i][j + 1] + bias[col + 1], 0.f);
            C2[j >> 1] = __floats2half2_rn(v0, v1);
        }
    }
}

// ================= FP16 tensor-core GEMM common helpers ======================
#define HSTR 72
#define HBUF (128*HSTR)
#define HSMEM (4*HBUF*2)

#define CPA16(dst, src) asm volatile("cp.async.cg.shared.global [%0], [%1], 16;" :: "r"(dst), "l"(src))

__device__ __forceinline__ void ldsm4(uint32_t (&r)[4], uint32_t addr) {
    asm volatile("ldmatrix.sync.aligned.m8n8.x4.shared.b16 {%0,%1,%2,%3}, [%4];"
                 : "=r"(r[0]), "=r"(r[1]), "=r"(r[2]), "=r"(r[3]) : "r"(addr));
}
__device__ __forceinline__ void ldsm4t(uint32_t (&r)[4], uint32_t addr) {
    asm volatile("ldmatrix.sync.aligned.m8n8.x4.trans.shared.b16 {%0,%1,%2,%3}, [%4];"
                 : "=r"(r[0]), "=r"(r[1]), "=r"(r[2]), "=r"(r[3]) : "r"(addr));
}

#define HMMA(d, a, b0, b1) asm volatile( \
    "mma.sync.aligned.m16n8k16.row.col.f32.f16.f16.f32 " \
    "{%0,%1,%2,%3}, {%4,%5,%6,%7}, {%8,%9}, {%0,%1,%2,%3};" \
    : "+f"(d[0]), "+f"(d[1]), "+f"(d[2]), "+f"(d[3]) \
    : "r"(a[0]), "r"(a[1]), "r"(a[2]), "r"(a[3]), "r"(b0), "r"(b1))

__device__ __forceinline__ uint32_t packh2(float a, float b) {
    __half2 h = __floats2half2_rn(a, b);
    return *(uint32_t*)&h;
}

// ================= hgemm: 128x128 tile (for N=768/1024 GEMMs) ===============
__global__ void __launch_bounds__(256, 2)
hgemm(const __half* __restrict__ A, const __half* __restrict__ Bt,
      const float* __restrict__ bias, void* __restrict__ Cv,
      int M, int N, int K, int lda, int ldc, int relu, int outh) {
    extern __shared__ __half shh[];
    const int tid  = threadIdx.x;
    const int lane = tid & 31;
    const int wid  = tid >> 5;
    const int wr   = wid >> 2;
    const int wc   = wid & 3;
    const int bm   = blockIdx.y * 128;
    const int bn   = blockIdx.x * 128;

    uint32_t sbase = (uint32_t)__cvta_generic_to_shared(shh);

    float acc[4][4][4];
#pragma unroll
    for (int mt = 0; mt < 4; mt++)
#pragma unroll
        for (int nt = 0; nt < 4; nt++)
#pragma unroll
            for (int r = 0; r < 4; r++) acc[mt][nt][r] = 0.0f;

#define HLOAD(buf, k0)                                                          \
    do {                                                                        \
        _Pragma("unroll")                                                       \
        for (int i = 0; i < 4; i++) {                                           \
            int idx = tid + i * 256;                                            \
            int r = idx >> 3, c = (idx & 7) << 3;                               \
            CPA16(sbase + (uint32_t)((buf) * HBUF + r * HSTR + c) * 2u,         \
                  A + (long)(bm + r) * lda + (k0) + c);                         \
        }                                                                       \
        _Pragma("unroll")                                                       \
        for (int i = 0; i < 4; i++) {                                           \
            int idx = tid + i * 256;                                            \
            int r = idx >> 3, c = (idx & 7) << 3;                               \
            CPA16(sbase + (uint32_t)((2 + (buf)) * HBUF + r * HSTR + c) * 2u,   \
                  Bt + (long)(bn + r) * K + (k0) + c);                          \
        }                                                                       \
        asm volatile("cp.async.commit_group;");                                 \
    } while (0)

    const int nk = K >> 6;
    HLOAD(0, 0);

    const int arow = wr * 64 + (lane & 15);
    const int ach  = (lane >> 4) << 3;
    const int brow16 = wc * 32 + (lane & 15);
    const int bch16  = (lane >> 4) << 3;

    for (int it = 0; it < nk; it++) {
        int cur = it & 1;
        if (it + 1 < nk) {
            HLOAD(cur ^ 1, (it + 1) << 6);
            asm volatile("cp.async.wait_group 1;");
        } else {
            asm volatile("cp.async.wait_group 0;");
        }
        __syncthreads();

        uint32_t aB = sbase + (uint32_t)(cur * HBUF) * 2u;
        uint32_t bB = sbase + (uint32_t)((2 + cur) * HBUF) * 2u;

#pragma unroll
        for (int ks = 0; ks < 4; ks++) {
            uint32_t af[4][4], bf[4][2];
#pragma unroll
            for (int mt = 0; mt < 4; mt++)
                ldsm4(af[mt], aB + (uint32_t)((arow + mt * 16) * HSTR + ks * 16 + ach) * 2u);
#pragma unroll
            for (int np = 0; np < 2; np++) {
                uint32_t br[4];
                ldsm4(br, bB + (uint32_t)((brow16 + np * 16) * HSTR + ks * 16 + bch16) * 2u);
                bf[2 * np][0] = br[0];     bf[2 * np][1] = br[2];
                bf[2 * np + 1][0] = br[1]; bf[2 * np + 1][1] = br[3];
            }
#pragma unroll
            for (int mt = 0; mt < 4; mt++)
#pragma unroll
                for (int nt = 0; nt < 4; nt++)
                    HMMA(acc[mt][nt], af[mt], bf[nt][0], bf[nt][1]);
        }
        __syncthreads();
    }

#pragma unroll
    for (int mt = 0; mt < 4; mt++) {
        int row = bm + wr * 64 + mt * 16 + (lane >> 2);
#pragma unroll
        for (int nt = 0; nt < 4; nt++) {
            int col = bn + wc * 32 + nt * 8 + ((lane & 3) << 1);
            float b0 = bias[col], b1 = bias[col + 1];
            float v0 = acc[mt][nt][0] + b0, v1 = acc[mt][nt][1] + b1;
            float v2 = acc[mt][nt][2] + b0, v3 = acc[mt][nt][3] + b1;
            if (relu) { v0 = fmaxf(v0, 0.f); v1 = fmaxf(v1, 0.f);
                        v2 = fmaxf(v2, 0.f); v3 = fmaxf(v3, 0.f); }
            if (outh) {
                __half2* C2 = (__half2*)Cv;
                C2[((long)row * ldc + col) >> 1]       = __floats2half2_rn(v0, v1);
                C2[((long)(row + 8) * ldc + col) >> 1] = __floats2half2_rn(v2, v3);
            } else {
                float* C = (float*)Cv;
                long i0 = (long)row * ldc + col;
                long i1 = i0 + 8L * ldc;
                C[i0] = v0; C[i0 + 1] = v1; C[i1] = v2; C[i1 + 1] = v3;
            }
        }
    }
#undef HLOAD
}

// ========== hgemm64: 128x64 tile (SAGE layers, N=256) ========================
#define A64BUF (128*HSTR)
#define B64BUF (64*HSTR)
#define HSMEM64 ((2*A64BUF + 2*B64BUF)*2)

__global__ void __launch_bounds__(256, 2)
hgemm64(const __half* __restrict__ A, const __half* __restrict__ Bt,
        const float* __restrict__ bias, void* __restrict__ Cv,
        int M, int N, int K, int lda, int ldc, int relu, int outh,
        float* __restrict__ outf) {
    extern __shared__ __half shh[];
    const int tid  = threadIdx.x;
    const int lane = tid & 31;
    const int wid  = tid >> 5;
    const int wr   = wid >> 1;
    const int wc   = wid & 1;
    const int bm   = blockIdx.y * 128;
    const int bn   = blockIdx.x * 64;

    uint32_t sbase = (uint32_t)__cvta_generic_to_shared(shh);

    float acc[2][4][4];
#pragma unroll
    for (int mt = 0; mt < 2; mt++)
#pragma unroll
        for (int nt = 0; nt < 4; nt++)
#pragma unroll
            for (int r = 0; r < 4; r++) acc[mt][nt][r] = 0.0f;

#define HLOAD64(buf, k0)                                                        \
    do {                                                                        \
        _Pragma("unroll")                                                       \
        for (int i = 0; i < 4; i++) {                                           \
            int idx = tid + i * 256;                                            \
            int r = idx >> 3, c = (idx & 7) << 3;                               \
            CPA16(sbase + (uint32_t)((buf) * A64BUF + r * HSTR + c) * 2u,       \
                  A + (long)(bm + r) * lda + (k0) + c);                         \
        }                                                                       \
        _Pragma("unroll")                                                       \
        for (int i = 0; i < 2; i++) {                                           \
            int idx = tid + i * 256;                                            \
            int r = idx >> 3, c = (idx & 7) << 3;                               \
            CPA16(sbase + (uint32_t)(2 * A64BUF + (buf) * B64BUF + r * HSTR + c) * 2u, \
                  Bt + (long)(bn + r) * K + (k0) + c);                          \
        }                                                                       \
        asm volatile("cp.async.commit_group;");                                 \
    } while (0)

    const int nk = K >> 6;
    HLOAD64(0, 0);

    const int arow = wr * 32 + (lane & 15);
    const int ach  = (lane >> 4) << 3;
    const int brow16 = wc * 32 + (lane & 15);
    const int bch16  = (lane >> 4) << 3;

    for (int it = 0; it < nk; it++) {
        int cur = it & 1;
        if (it + 1 < nk) {
            HLOAD64(cur ^ 1, (it + 1) << 6);
            asm volatile("cp.async.wait_group 1;");
        } else {
            asm volatile("cp.async.wait_group 0;");
        }
        __syncthreads();

        uint32_t aB = sbase + (uint32_t)(cur * A64BUF) * 2u;
        uint32_t bB = sbase + (uint32_t)(2 * A64BUF + cur * B64BUF) * 2u;

#pragma unroll
        for (int ks = 0; ks < 4; ks++) {
            uint32_t af[2][4], bf[4][2];
#pragma unroll
            for (int mt = 0; mt < 2; mt++)
                ldsm4(af[mt], aB + (uint32_t)((arow + mt * 16) * HSTR + ks * 16 + ach) * 2u);
#pragma unroll
            for (int np = 0; np < 2; np++) {
                uint32_t br[4];
                ldsm4(br, bB + (uint32_t)((brow16 + np * 16) * HSTR + ks * 16 + bch16) * 2u);
                bf[2 * np][0] = br[0];     bf[2 * np][1] = br[2];
                bf[2 * np + 1][0] = br[1]; bf[2 * np + 1][1] = br[3];
            }
#pragma unroll
            for (int mt = 0; mt < 2; mt++)
#pragma unroll
                for (int nt = 0; nt < 4; nt++)
                    HMMA(acc[mt][nt], af[mt], bf[nt][0], bf[nt][1]);
        }
        __syncthreads();
    }

#pragma unroll
    for (int mt = 0; mt < 2; mt++) {
        long row = bm + wr * 32 + mt * 16 + (lane >> 2);
#pragma unroll
        for (int nt = 0; nt < 4; nt++) {
            int col = bn + wc * 32 + nt * 8 + ((lane & 3) << 1);
            float b0 = bias[col], b1 = bias[col + 1];
            float v0 = acc[mt][nt][0] + b0, v1 = acc[mt][nt][1] + b1;
            float v2 = acc[mt][nt][2] + b0, v3 = acc[mt][nt][3] + b1;
            if (relu) { v0 = fmaxf(v0, 0.f); v1 = fmaxf(v1, 0.f);
                        v2 = fmaxf(v2, 0.f); v3 = fmaxf(v3, 0.f); }
            if (outf) {
                *(float2*)(outf + row * ldc + col) = make_float2(v0, v1);
                *(float2*)(outf + (row + 8) * ldc + col) = make_float2(v2, v3);
            }
            if (outh) {
                __half2* C2 = (__half2*)Cv;
                C2[(row * ldc + col) >> 1]       = __floats2half2_rn(v0, v1);
                C2[((row + 8) * ldc + col) >> 1] = __floats2half2_rn(v2, v3);
            }
        }
    }
#undef HLOAD64
}

// ===== hgemm_ln: 64x256 tile GEMM + bias + residual + LayerNorm epilogue ====
#define LNA (64*HSTR)
#define LNB (256*HSTR)
#define HSMEM_LN ((2*LNA + 2*LNB)*2)

__global__ void __launch_bounds__(256, 2)
hgemm_ln(const __half* __restrict__ A, const __half* __restrict__ Bt,
         const float* __restrict__ bias, const float* __restrict__ resid,
         const float* __restrict__ gamma, const float* __restrict__ beta,
         float* __restrict__ outf, __half* __restrict__ outh, int K) {
    extern __shared__ __half shh[];
    __shared__ float red[64][4];
    const int tid  = threadIdx.x;
    const int lane = tid & 31;
    const int wid  = tid >> 5;
    const int wr   = wid >> 2;
    const int wc   = wid & 3;
    const long bm  = (long)blockIdx.x * 64;

    uint32_t sbase = (uint32_t)__cvta_generic_to_shared(shh);

    float acc[2][8][4];
#pragma unroll
    for (int mt = 0; mt < 2; mt++)
#pragma unroll
        for (int nt = 0; nt < 8; nt++)
#pragma unroll
            for (int r = 0; r < 4; r++) acc[mt][nt][r] = 0.0f;

#define LNLOAD(buf, k0)                                                         \
    do {                                                                        \
        _Pragma("unroll")                                                       \
        for (int i = 0; i < 2; i++) {                                           \
            int idx = tid + i * 256;                                            \
            int r = idx >> 3, c = (idx & 7) << 3;                               \
            CPA16(sbase + (uint32_t)((buf) * LNA + r * HSTR + c) * 2u,          \
                  A + (bm + r) * K + (k0) + c);                                 \
        }                                                                       \
        _Pragma("unroll")                                                       \
        for (int i = 0; i < 8; i++) {                                           \
            int idx = tid + i * 256;                                            \
            int r = idx >> 3, c = (idx & 7) << 3;                               \
            CPA16(sbase + (uint32_t)(2 * LNA + (buf) * LNB + r * HSTR + c) * 2u,\
                  Bt + (long)r * K + (k0) + c);                                 \
        }                                                                       \
        asm volatile("cp.async.commit_group;");                                 \
    } while (0)

    const int nk = K >> 6;
    LNLOAD(0, 0);

    const int arowb = wr * 32 + (lane & 15);
    const int ach   = (lane >> 4) << 3;
    const int browb = wc * 64 + (lane & 7) + ((lane >> 4) << 3);
    const int bch   = lane & 8;

    for (int it = 0; it < nk; it++) {
        int cur = it & 1;
        if (it + 1 < nk) {
            LNLOAD(cur ^ 1, (it + 1) << 6);
            asm volatile("cp.async.wait_group 1;");
        } else {
            asm volatile("cp.async.wait_group 0;");
        }
        __syncthreads();

        uint32_t aB = sbase + (uint32_t)(cur * LNA) * 2u;
        uint32_t bB = sbase + (uint32_t)(2 * LNA + cur * LNB) * 2u;

#pragma unroll
        for (int ks = 0; ks < 4; ks++) {
            uint32_t af[2][4];
#pragma unroll
            for (int mt = 0; mt < 2; mt++)
                ldsm4(af[mt], aB + (uint32_t)((arowb + mt * 16) * HSTR + ks * 16 + ach) * 2u);
#pragma unroll
            for (int np = 0; np < 4; np++) {
                uint32_t kf[4];
                ldsm4(kf, bB + (uint32_t)((browb + np * 16) * HSTR + ks * 16 + bch) * 2u);
#pragma unroll
                for (int mt = 0; mt < 2; mt++) {
                    HMMA(acc[mt][2 * np],     af[mt], kf[0], kf[1]);
                    HMMA(acc[mt][2 * np + 1], af[mt], kf[2], kf[3]);
                }
            }
        }
        __syncthreads();
    }

    const int q = lane >> 2, t2 = (lane & 3) << 1;
#pragma unroll
    for (int mt = 0; mt < 2; mt++) {
        long r0 = bm + wr * 32 + mt * 16 + q;
        long r1 = r0 + 8;
        float s0 = 0.f, s1 = 0.f;
#pragma unroll
        for (int nt = 0; nt < 8; nt++) {
            int col = wc * 64 + nt * 8 + t2;
            float b0 = bias[col], b1 = bias[col + 1];
            float2 q0 = *(const float2*)(resid + r0 * 256 + col);
            float2 q1 = *(const float2*)(resid + r1 * 256 + col);
            acc[mt][nt][0] += b0 + q0.x; acc[mt][nt][1] += b1 + q0.y;
            acc[mt][nt][2] += b0 + q1.x; acc[mt][nt][3] += b1 + q1.y;
            s0 += acc[mt][nt][0] + acc[mt][nt][1];
            s1 += acc[mt][nt][2] + acc[mt][nt][3];
        }
        s0 += __shfl_xor_sync(0xffffffffu, s0, 1);
        s0 += __shfl_xor_sync(0xffffffffu, s0, 2);
        s1 += __shfl_xor_sync(0xffffffffu, s1, 1);
        s1 += __shfl_xor_sync(0xffffffffu, s1, 2);
        int lr = wr * 32 + mt * 16 + q;
        if ((lane & 3) == 0) { red[lr][wc] = s0; red[lr + 8][wc] = s1; }
    }
    __syncthreads();
    float mean[2][2];
#pragma unroll
    for (int mt = 0; mt < 2; mt++) {
        int lr = wr * 32 + mt * 16 + q;
        mean[mt][0] = (red[lr][0] + red[lr][1] + red[lr][2] + red[lr][3]) * (1.0f / EMBD);
        mean[mt][1] = (red[lr + 8][0] + red[lr + 8][1] + red[lr + 8][2] + red[lr + 8][3]) * (1.0f / EMBD);
    }
    __syncthreads();
#pragma unroll
    for (int mt = 0; mt < 2; mt++) {
        float s0 = 0.f, s1 = 0.f;
#pragma unroll
        for (int nt = 0; nt < 8; nt++) {
            float d0 = acc[mt][nt][0] - mean[mt][0];
            float d1 = acc[mt][nt][1] - mean[mt][0];
            float d2 = acc[mt][nt][2] - mean[mt][1];
            float d3 = acc[mt][nt][3] - mean[mt][1];
            s0 += d0 * d0 + d1 * d1;
            s1 += d2 * d2 + d3 * d3;
        }
        s0 += __shfl_xor_sync(0xffffffffu, s0, 1);
        s0 += __shfl_xor_sync(0xffffffffu, s0, 2);
        s1 += __shfl_xor_sync(0xffffffffu, s1, 1);
        s1 += __shfl_xor_sync(0xffffffffu, s1, 2);
        int lr = wr * 32 + mt * 16 + q;
        if ((lane & 3) == 0) { red[lr][wc] = s0; red[lr + 8][wc] = s1; }
    }
    __syncthreads();
#pragma unroll
    for (int mt = 0; mt < 2; mt++) {
        int lr = wr * 32 + mt * 16 + q;
        float rstd0 = rsqrtf((red[lr][0] + red[lr][1] + red[lr][2] + red[lr][3]) * (1.0f / EMBD) + 1e-5f);
        float rstd1 = rsqrtf((red[lr + 8][0] + red[lr + 8][1] + red[lr + 8][2] + red[lr + 8][3]) * (1.0f / EMBD) + 1e-5f);
        long r0 = bm + lr;
        long r1 = r0 + 8;
#pragma unroll
        for (int nt = 0; nt < 8; nt++) {
            int col = wc * 64 + nt * 8 + t2;
            float g0 = gamma[col], g1 = gamma[col + 1];
            float e0 = beta[col],  e1 = beta[col + 1];
            float o0 = (acc[mt][nt][0] - mean[mt][0]) * rstd0 * g0 + e0;
            float o1 = (acc[mt][nt][1] - mean[mt][0]) * rstd0 * g1 + e1;
            float o2 = (acc[mt][nt][2] - mean[mt][1]) * rstd1 * g0 + e0;
            float o3 = (acc[mt][nt][3] - mean[mt][1]) * rstd1 * g1 + e1;
            *(float2*)(outf + r0 * 256 + col) = make_float2(o0, o1);
            *(float2*)(outf + r1 * 256 + col) = make_float2(o2, o3);
            if (outh) {
                *(__half2*)(outh + r0 * 256 + col) = __floats2half2_rn(o0, o1);
                *(__half2*)(outh + r1 * 256 + col) = __floats2half2_rn(o2, o3);
            }
        }
    }
#undef LNLOAD
}

// ============ compact flash attention + fused pad-rep: block per (g, h) =====
#define ATT_SMEM (2*320*40*2 + 320*4)

__global__ void __launch_bounds__(128, 4)
attn_mma(const __half* __restrict__ qkv, const int* __restrict__ batches,
         __half* __restrict__ oh) {
    int g = blockIdx.x, h = blockIdx.y;
    int st = batches[g];
    int len = batches[g + 1] - st;
    extern __shared__ __half smh[];
    uint32_t sb = (uint32_t)__cvta_generic_to_shared(smh);
    const uint32_t voff = 320u * 40u * 2u;
    float* spf = (float*)(smh + 2 * 320 * 40);
    __shared__ float qsh[DHD];
    __shared__ float s_sm;
    __shared__ float av[4][DHD];

    int tid = threadIdx.x;
    for (int idx = tid; idx < len * 4; idx += 128) {
        int l = idx >> 2, c = idx & 3;
        const __half* srcK = qkv + (long)(st + l) * 768 + 256 + h * 32 + c * 8;
        uint32_t d = (uint32_t)(l * 40 + c * 8) * 2u;
        CPA16(sb + d, srcK);
        CPA16(sb + voff + d, srcK + 256);
    }
    asm volatile("cp.async.commit_group;");
    if (tid < DHD)
        qsh[tid] = __half2float(qkv[(long)(NN + g) * 768 + h * 32 + tid]);
    asm volatile("cp.async.wait_group 0;");
    __syncthreads();

    const int w = tid >> 5, lane = tid & 31;
    const int r = lane >> 2, t = lane & 3;
    const int nch = len >> 6;
    const int ntiles = len >> 4;
    const float scale = 0.17677669529663687f;

    for (int mt = w; mt < ntiles; mt += 4) {
        long q0row = (long)(st + mt * 16 + r);
        uint32_t qf[2][4];
        {
            const __half* q0 = qkv + q0row * 768 + h * 32;
            const __half* q1 = q0 + 8L * 768;
#pragma unroll
            for (int ks = 0; ks < 2; ks++) {
                int c0 = ks * 16 + 2 * t;
                qf[ks][0] = *(const uint32_t*)(q0 + c0);
                qf[ks][1] = *(const uint32_t*)(q1 + c0);
                qf[ks][2] = *(const uint32_t*)(q0 + c0 + 8);
                qf[ks][3] = *(const uint32_t*)(q1 + c0 + 8);
            }
        }
        float o_[4][4];
#pragma unroll
        for (int nt = 0; nt < 4; nt++)
#pragma unroll
            for (int j = 0; j < 4; j++) o_[nt][j] = 0.f;
        float mx0 = -3e38f, mx1 = -3e38f, sm0 = 0.f, sm1 = 0.f;

        for (int ch = 0; ch < nch; ch++) {
            int base = ch << 6;
            float s[8][4];
#pragma unroll
            for (int nt = 0; nt < 8; nt++)
#pragma unroll
                for (int j = 0; j < 4; j++) s[nt][j] = 0.f;

#pragma unroll
            for (int ks = 0; ks < 2; ks++) {
#pragma unroll
                for (int np = 0; np < 4; np++) {
                    uint32_t kf[4];
                    int krow = base + np * 16 + (lane & 7) + ((lane >> 4) << 3);
                    int kcol = ks * 16 + (lane & 8);
                    ldsm4(kf, sb + (uint32_t)(krow * 40 + kcol) * 2u);
                    HMMA(s[2 * np],     qf[ks], kf[0], kf[1]);
                    HMMA(s[2 * np + 1], qf[ks], kf[2], kf[3]);
                }
            }

            float cm0 = -3e38f, cm1 = -3e38f;
#pragma unroll
            for (int nt = 0; nt < 8; nt++) {
                cm0 = fmaxf(cm0, fmaxf(s[nt][0], s[nt][1]));
                cm1 = fmaxf(cm1, fmaxf(s[nt][2], s[nt][3]));
            }
            cm0 = fmaxf(cm0, __shfl_xor_sync(0xffffffffu, cm0, 1));
            cm0 = fmaxf(cm0, __shfl_xor_sync(0xffffffffu, cm0, 2));
            cm1 = fmaxf(cm1, __shfl_xor_sync(0xffffffffu, cm1, 1));
            cm1 = fmaxf(cm1, __shfl_xor_sync(0xffffffffu, cm1, 2));
            float nm0 = fmaxf(mx0, cm0), nm1 = fmaxf(mx1, cm1);
            float corr0 = __expf((mx0 - nm0) * scale);
            float corr1 = __expf((mx1 - nm1) * scale);
            mx0 = nm0; mx1 = nm1;

            uint32_t pf[4][4];
            float ps0 = 0.f, ps1 = 0.f;
#pragma unroll
            for (int kf = 0; kf < 4; kf++) {
                float p00 = __expf((s[2 * kf][0] - nm0) * scale);
                float p01 = __expf((s[2 * kf][1] - nm0) * scale);
                float p02 = __expf((s[2 * kf][2] - nm1) * scale);
                float p03 = __expf((s[2 * kf][3] - nm1) * scale);
                float p10 = __expf((s[2 * kf + 1][0] - nm0) * scale);
                float p11 = __expf((s[2 * kf + 1][1] - nm0) * scale);
                float p12 = __expf((s[2 * kf + 1][2] - nm1) * scale);
                float p13 = __expf((s[2 * kf + 1][3] - nm1) * scale);
                ps0 += (p00 + p01) + (p10 + p11);
                ps1 += (p02 + p03) + (p12 + p13);
                pf[kf][0] = packh2(p00, p01);
                pf[kf][1] = packh2(p02, p03);
                pf[kf][2] = packh2(p10, p11);
                pf[kf][3] = packh2(p12, p13);
            }
            sm0 = sm0 * corr0 + ps0;
            sm1 = sm1 * corr1 + ps1;
#pragma unroll
            for (int nt = 0; nt < 4; nt++) {
                o_[nt][0] *= corr0; o_[nt][1] *= corr0;
                o_[nt][2] *= corr1; o_[nt][3] *= corr1;
            }

#pragma unroll
            for (int kf = 0; kf < 4; kf++) {
                int k0 = base + kf * 16;
                uint32_t vrow = (uint32_t)((k0 + (lane & 15)) * 40 + ((lane >> 4) << 3));
                uint32_t vf[4];
                ldsm4t(vf, sb + voff + vrow * 2u);
                HMMA(o_[0], pf[kf], vf[0], vf[1]);
                HMMA(o_[1], pf[kf], vf[2], vf[3]);
                ldsm4t(vf, sb + voff + (vrow + 16u) * 2u);
                HMMA(o_[2], pf[kf], vf[0], vf[1]);
                HMMA(o_[3], pf[kf], vf[2], vf[3]);
            }
        }

        float rs0 = sm0 + __shfl_xor_sync(0xffffffffu, sm0, 1);
        rs0 += __shfl_xor_sync(0xffffffffu, rs0, 2);
        float rs1 = sm1 + __shfl_xor_sync(0xffffffffu, sm1, 1);
        rs1 += __shfl_xor_sync(0xffffffffu, rs1, 2);
        float inv0 = 1.f / rs0, inv1 = 1.f / rs1;
        long r0base = q0row * 256 + h * 32 + 2 * t;
        long r1base = r0base + 8L * 256;
#pragma unroll
        for (int nt = 0; nt < 4; nt++) {
            *(__half2*)(oh + r0base + nt * 8) = __floats2half2_rn(o_[nt][0] * inv0, o_[nt][1] * inv0);
            *(__half2*)(oh + r1base + nt * 8) = __floats2half2_rn(o_[nt][2] * inv1, o_[nt][3] * inv1);
        }
    }

    // ---- fused pad-rep attention for row NN+g using staged smem K/V ----
    __syncthreads();
    for (int m = tid; m < len; m += 128) {
        const __half2* kr = (const __half2*)(smh + m * 40);
        float s = 0.f;
#pragma unroll
        for (int d = 0; d < 16; d++) {
            float2 k2 = __half22float2(kr[d]);
            s = fmaf(qsh[2 * d], k2.x, s);
            s = fmaf(qsh[2 * d + 1], k2.y, s);
        }
        spf[m] = s;
    }
    __syncthreads();
    if (tid < 32) {
        float mx = -3e38f;
        for (int m = tid; m < len; m += 32) mx = fmaxf(mx, spf[m]);
#pragma unroll
        for (int off = 16; off; off >>= 1)
            mx = fmaxf(mx, __shfl_xor_sync(0xffffffffu, mx, off));
        float sm = 0.f;
        for (int m = tid; m < len; m += 32) {
            float p = __expf((spf[m] - mx) * 0.17677669529663687f);
            spf[m] = p;
            sm += p;
        }
#pragma unroll
        for (int off = 16; off; off >>= 1)
            sm += __shfl_xor_sync(0xffffffffu, sm, off);
        if (tid == 0) s_sm = sm;
    }
    __syncthreads();
    int d = tid & 31, wq = tid >> 5;
    float acc = 0.f;
    for (int m = wq; m < len; m += 4)
        acc = fmaf(spf[m], __half2float(smh[320 * 40 + m * 40 + d]), acc);
    av[wq][d] = acc;
    __syncthreads();
    if (tid < 32) {
        float a = ((av[0][tid] + av[1][tid]) + (av[2][tid] + av[3][tid])) / s_sm;
        oh[(long)(NN + g) * 256 + h * 32 + tid] = __float2half(a);
    }
}

// ---------------- host orchestration ----------------------------------------
static void run_hgemm(const __half* A, const __half* Bt, const float* bias, void* C,
                      int M, int N, int K, int lda, int ldc, int relu, int outh) {
    dim3 grid(N / 128, M / 128);
    hgemm<<<grid, 256, HSMEM>>>(A, Bt, bias, C, M, N, K, lda, ldc, relu, outh);
}

static void run_hgemm64(const __half* A, const __half* Bt, const float* bias, void* C,
                        int M, int N, int K, int lda, int ldc, int relu, int outh,
                        float* outf) {
    dim3 grid(N / 64, M / 128);
    hgemm64<<<grid, 256, HSMEM64>>>(A, Bt, bias, C, M, N, K, lda, ldc, relu, outh, outf);
}

extern "C" void kernel_launch(void* const* d_in, const int* in_sizes, int n_in,
                              void* d_out, int out_size) {
    const float* x       = (const float*)d_in[0];
    const int*   ei      = (const int*)d_in[1];
    const int*   batches = (const int*)d_in[2];

    int wi = 3;
    if (n_in >= 29 && in_sizes[3] == 1) wi = 4;

    const float* sW0  = (const float*)d_in[wi++];
    const float* sWn0 = (const float*)d_in[wi++];
    const float* sb0  = (const float*)d_in[wi++];
    const float* sW1  = (const float*)d_in[wi++];
    const float* sWn1 = (const float*)d_in[wi++];
    const float* sb1  = (const float*)d_in[wi++];
    const float* sW2  = (const float*)d_in[wi++];
    const float* sWn2 = (const float*)d_in[wi++];
    const float* sb2  = (const float*)d_in[wi++];
    const float* Wq   = (const float*)d_in[wi++];
    const float* Wk   = (const float*)d_in[wi++];
    const float* Wv   = (const float*)d_in[wi++];
    const float* bq   = (const float*)d_in[wi++];
    const float* bk   = (const float*)d_in[wi++];
    const float* bv   = (const float*)d_in[wi++];
    const float* Wo   = (const float*)d_in[wi++];
    const float* bo   = (const float*)d_in[wi++];
    const float* ln1g = (const float*)d_in[wi++];
    const float* ln1b = (const float*)d_in[wi++];
    const float* ln2g = (const float*)d_in[wi++];
    const float* ln2b = (const float*)d_in[wi++];
    const float* W1   = (const float*)d_in[wi++];
    const float* b1   = (const float*)d_in[wi++];
    const float* W2   = (const float*)d_in[wi++];
    const float* b2   = (const float*)d_in[wi++];

    int *rowptr, *cnt, *csrc, *bsum;
    float *comb0, *wsg0, *hp, *bqkv;
    __half *comb1h, *comb2h, *hph, *qkvh, *oh, *midh;
    __half *wsg1t, *wsg2t, *wqkvt, *wot, *w1t, *w2t;
    cudaGetSymbolAddress((void**)&rowptr, g_rowptr);
    cudaGetSymbolAddress((void**)&cnt,    g_cnt);
    cudaGetSymbolAddress((void**)&csrc,   g_csrc);
    cudaGetSymbolAddress((void**)&bsum,   g_bsum);
    cudaGetSymbolAddress((void**)&comb0,  g_comb0);
    cudaGetSymbolAddress((void**)&wsg0,   g_wsg0);
    cudaGetSymbolAddress((void**)&comb1h, g_comb1h);
    cudaGetSymbolAddress((void**)&comb2h, g_comb2h);
    cudaGetSymbolAddress((void**)&hp,     g_hp);
    cudaGetSymbolAddress((void**)&hph,    g_hph);
    cudaGetSymbolAddress((void**)&qkvh,   g_qkvh);
    cudaGetSymbolAddress((void**)&oh,     g_oh);
    cudaGetSymbolAddress((void**)&midh,   g_midh);
    cudaGetSymbolAddress((void**)&wsg1t,  g_wsg1t);
    cudaGetSymbolAddress((void**)&wsg2t,  g_wsg2t);
    cudaGetSymbolAddress((void**)&wqkvt,  g_wqkvt);
    cudaGetSymbolAddress((void**)&wot,    g_wot);
    cudaGetSymbolAddress((void**)&w1t,    g_w1t);
    cudaGetSymbolAddress((void**)&w2t,    g_w2t);
    cudaGetSymbolAddress((void**)&bqkv,   g_bqkv);

    cudaFuncSetAttribute(attn_mma, cudaFuncAttributeMaxDynamicSharedMemorySize, ATT_SMEM);
    cudaFuncSetAttribute(hgemm, cudaFuncAttributeMaxDynamicSharedMemorySize, HSMEM);
    cudaFuncSetAttribute(hgemm64, cudaFuncAttributeMaxDynamicSharedMemorySize, HSMEM64);
    cudaFuncSetAttribute(hgemm_ln, cudaFuncAttributeMaxDynamicSharedMemorySize, HSMEM_LN);

    // ---- all weight transposes in one launch ----
    TJobs J;
    const float* srcs[10] = {sW1, sWn1, sW2, sWn2, Wq, Wk, Wv, Wo, W1, W2};
    __half* dsts[10] = {wsg1t, wsg1t + 256, wsg2t, wsg2t + 256,
                        wqkvt, wqkvt + 65536, wqkvt + 131072, wot, w1t, w2t};
    int gxs[10]  = {8, 8, 8, 8, 8, 8, 8, 8, 32, 8};
    int gys[10]  = {8, 8, 8, 8, 8, 8, 8, 8, 8, 32};
    int nzs[10]  = {1, 1, 1, 1, 4, 4, 4, 4, 4, 4};
    int Ns[10]   = {256, 256, 256, 256, 256, 256, 256, 256, 1024, 256};
    int ldds[10] = {512, 512, 512, 512, 256, 256, 256, 256, 256, 1024};
    long slss[10] = {0, 0, 0, 0, 65536, 65536, 65536, 65536, 262144, 262144};
    long dlss[10] = {0, 0, 0, 0, 196608, 196608, 196608, 65536, 262144, 262144};
    int acc = 0;
    for (int i = 0; i < 10; i++) {
        J.src[i] = srcs[i]; J.dst[i] = dsts[i];
        J.gx[i] = gxs[i]; J.gy[i] = gys[i]; J.N[i] = Ns[i]; J.ldd[i] = ldds[i];
        J.sls[i] = slss[i]; J.dls[i] = dlss[i];
        J.base[i] = acc;
        acc += gxs[i] * gys[i] * nzs[i];
    }
    J.base[10] = acc;
    transpose_all<<<acc, dim3(32, 8)>>>(J);
    misc_pack<<<172, 256>>>(hp, hph, oh, sW0, sWn0, wsg0, bq, bk, bv, bqkv);

    // ---- CSR build (parallel 3-phase scan; cnt zeroed by previous replay's
    //      agg0_kernel, and statically zero on the very first run) ----
    degi_kernel<<<(NE + 255) / 256, 256>>>(ei, cnt);
    scan_local<<<NN / 256, 256>>>(cnt, rowptr, bsum);
    scan_bsum<<<1, 32>>>(bsum);
    scan_add<<<NN / 256, 256>>>(rowptr, bsum);
    fill_kernel<<<(NE + 255) / 256, 256>>>(ei, cnt, csrc);

    // ---- SAGE layer 0 (also re-zeroes cnt for next replay) ----
    agg0_kernel<<<NN / 8, 256>>>(x, comb0, cnt);
    gemm32h_kernel<<<dim3(256 / BN, NN / BM), 256>>>(comb0, wsg0, sb0, comb1h, 512);

    // ---- SAGE layer 1 ----
    agg_csr_h<<<NN, 128>>>(comb1h);
    run_hgemm64(comb1h, wsg1t, sb1, comb2h, NN, 256, 512, 512, 512, 1, 1, nullptr);

    // ---- SAGE layer 2: write compact hp (fp32) + hph (half) directly -------
    agg_csr_h<<<NN, 128>>>(comb2h);
    run_hgemm64(comb2h, wsg2t, sb2, hph, NN, 256, 512, 512, 256, 0, 1, hp);

    // ---- 4 transformer layers on compact rows [0, MTOT) ----
    for (int l = 0; l < 4; l++) {
        run_hgemm(hph, wqkvt + (long)l * 196608, bqkv + l * 768, qkvh,
                  MTOT, 768, 256, 256, 768, 0, 1);

        attn_mma<<<dim3(NG, NHD), 128, ATT_SMEM>>>(qkvh, batches, oh);

        hgemm_ln<<<MTOT / 64, 256, HSMEM_LN>>>(
            oh, wot + (long)l * 65536, bo + l * 256, hp,
            ln1g + l * EMBD, ln1b + l * EMBD, hp, hph, 256);

        run_hgemm(hph, w1t + (long)l * 262144, b1 + l * FFND, midh,
                  MTOT, 1024, 256, 256, 1024, 1, 1);

        hgemm_ln<<<MTOT / 64, 256, HSMEM_LN>>>(
            midh, w2t + (long)l * 262144, b2 + l * 256, hp,
            ln2g + l * EMBD, ln2b + l * EMBD, hp, (l < 3) ? hph : nullptr, 1024);
    }

    // ---- expand compact -> [LMAX, NG, EMB] with pad broadcast ----
    scatter_out<<<dim3(LMAXC, NG), EMBD>>>(hp, batches, (float*)d_out);
}